// round 2
// baseline (speedup 1.0000x reference)
#include <cuda_runtime.h>
#include <math.h>

// ---------------- problem constants ----------------
#define NLAYERS 4
#define DMODEL  512
#define NHEAD   8
#define HDIM    64
#define DFF     2048
#define BATCH   8
#define SEQ     1024
#define MROWS   (BATCH*SEQ)          // 8192
#define LN_EPS  1e-3f

// ---------------- device scratch (allocation-free) ----------------
__device__ float g_x   [MROWS*DMODEL];
__device__ float g_h   [MROWS*DMODEL];
__device__ float g_q   [MROWS*DMODEL];
__device__ float g_k   [MROWS*DMODEL];
__device__ float g_v   [MROWS*DMODEL];
__device__ float g_attn[MROWS*DMODEL];
__device__ float g_ffn [MROWS*DFF];

// ---------------- positional encoding + add ----------------
__global__ void posenc_kernel(const float* __restrict__ x, float* __restrict__ out) {
    int idx = blockIdx.x * 256 + threadIdx.x;
    if (idx >= MROWS * DMODEL) return;
    int d = idx & (DMODEL - 1);
    int s = (idx / DMODEL) & (SEQ - 1);
    const int half = DMODEL / 2;  // 256
    float val;
    if (d < half) {
        float ang = (float)s * expf(-logf(10000.0f) * (2.0f * (float)d / (float)DMODEL));
        val = sinf(ang);
    } else {
        float j = (float)(d - half);
        float ang = (float)s * expf(-logf(10000.0f) * (2.0f * j / (float)DMODEL));
        val = cosf(ang);
    }
    out[idx] = x[idx] + val;
}

// ---------------- layernorm: one block (128 thr) per row of 512 ----------------
__global__ void ln_kernel(const float* __restrict__ x, const float* __restrict__ gamma,
                          const float* __restrict__ beta, float* __restrict__ out) {
    int row = blockIdx.x;
    int t = threadIdx.x;              // 0..127
    const float4* xr = (const float4*)(x + (size_t)row * DMODEL);
    float4 v = xr[t];

    __shared__ float red1[4];
    __shared__ float red2[4];

    float s = v.x + v.y + v.z + v.w;
    #pragma unroll
    for (int o = 16; o > 0; o >>= 1) s += __shfl_xor_sync(0xffffffffu, s, o);
    if ((t & 31) == 0) red1[t >> 5] = s;
    __syncthreads();
    float mean = (red1[0] + red1[1] + red1[2] + red1[3]) * (1.0f / DMODEL);

    float dx = v.x - mean, dy = v.y - mean, dz = v.z - mean, dw = v.w - mean;
    float s2 = dx*dx + dy*dy + dz*dz + dw*dw;
    #pragma unroll
    for (int o = 16; o > 0; o >>= 1) s2 += __shfl_xor_sync(0xffffffffu, s2, o);
    if ((t & 31) == 0) red2[t >> 5] = s2;
    __syncthreads();
    float var = (red2[0] + red2[1] + red2[2] + red2[3]) * (1.0f / DMODEL);
    float rs = rsqrtf(var + LN_EPS);

    float4 g4 = ((const float4*)gamma)[t];
    float4 b4 = ((const float4*)beta)[t];
    float4 o4;
    o4.x = dx * rs * g4.x + b4.x;
    o4.y = dy * rs * g4.y + b4.y;
    o4.z = dz * rs * g4.z + b4.z;
    o4.w = dw * rs * g4.w + b4.w;
    ((float4*)(out + (size_t)row * DMODEL))[t] = o4;
}

// ---------------- SGEMM 128x128x8, 256 threads, 8x8 microtile ----------------
// C[M,N] = A[M,K] @ W[K,N]   (all row-major)
// EPI: 0 = plain, 1 = + res, 2 = relu(+bias), 3 = + bias + res
template<int EPI>
__global__ __launch_bounds__(256) void gemm128(
    const float* __restrict__ A, const float* __restrict__ W,
    const float* __restrict__ bias, const float* __restrict__ res,
    float* __restrict__ C, int K, int N)
{
    __shared__ float As[8][128];
    __shared__ float Bs[8][128];

    int tid = threadIdx.x;
    int bx = blockIdx.x, by = blockIdx.y;

    int arow = tid >> 1;              // 0..127
    int ac   = (tid & 1) * 4;         // 0 or 4
    int brow = tid >> 5;              // 0..7
    int bc   = (tid & 31) * 4;        // 0..124

    const float* Aptr = A + ((size_t)(by * 128 + arow)) * K + ac;
    const float* Wptr = W + (size_t)brow * N + bx * 128 + bc;

    int ty = tid >> 4, tx = tid & 15;

    float acc[8][8];
    #pragma unroll
    for (int i = 0; i < 8; i++)
        #pragma unroll
        for (int j = 0; j < 8; j++) acc[i][j] = 0.0f;

    for (int kt = 0; kt < K; kt += 8) {
        float4 a4 = *(const float4*)(Aptr + kt);
        As[ac + 0][arow] = a4.x;
        As[ac + 1][arow] = a4.y;
        As[ac + 2][arow] = a4.z;
        As[ac + 3][arow] = a4.w;
        *(float4*)&Bs[brow][bc] = *(const float4*)(Wptr + (size_t)kt * N);
        __syncthreads();

        #pragma unroll
        for (int kk = 0; kk < 8; kk++) {
            float a[8], b[8];
            *(float4*)&a[0] = *(float4*)&As[kk][ty * 8];
            *(float4*)&a[4] = *(float4*)&As[kk][ty * 8 + 4];
            *(float4*)&b[0] = *(float4*)&Bs[kk][tx * 8];
            *(float4*)&b[4] = *(float4*)&Bs[kk][tx * 8 + 4];
            #pragma unroll
            for (int i = 0; i < 8; i++)
                #pragma unroll
                for (int j = 0; j < 8; j++)
                    acc[i][j] += a[i] * b[j];
        }
        __syncthreads();
    }

    #pragma unroll
    for (int i = 0; i < 8; i++) {
        int row = by * 128 + ty * 8 + i;
        #pragma unroll
        for (int jj = 0; jj < 8; jj += 4) {
            int col = bx * 128 + tx * 8 + jj;
            float4 o;
            o.x = acc[i][jj + 0];
            o.y = acc[i][jj + 1];
            o.z = acc[i][jj + 2];
            o.w = acc[i][jj + 3];
            if (EPI == 2 || EPI == 3) {
                const float4 bb = *(const float4*)(bias + col);
                o.x += bb.x; o.y += bb.y; o.z += bb.z; o.w += bb.w;
            }
            if (EPI == 2) {
                o.x = fmaxf(o.x, 0.0f); o.y = fmaxf(o.y, 0.0f);
                o.z = fmaxf(o.z, 0.0f); o.w = fmaxf(o.w, 0.0f);
            }
            if (EPI == 1 || EPI == 3) {
                const float4 rr = *(const float4*)(res + (size_t)row * N + col);
                o.x += rr.x; o.y += rr.y; o.z += rr.z; o.w += rr.w;
            }
            *(float4*)(C + (size_t)row * N + col) = o;
        }
    }
}

// ---------------- flash attention: one CTA per (b,h, 64-query tile) ----------------
#define AT_STRIDE 68
#define ATT_SMEM ((4 * 64 * AT_STRIDE + 64) * (int)sizeof(float))

__global__ __launch_bounds__(256) void attn_kernel(
    const float* __restrict__ q, const float* __restrict__ k,
    const float* __restrict__ v, const int* __restrict__ mask,
    float* __restrict__ out)
{
    extern __shared__ float smem[];
    float* Qs = smem;
    float* Ks = Qs + 64 * AT_STRIDE;
    float* Vs = Ks + 64 * AT_STRIDE;
    float* Ps = Vs + 64 * AT_STRIDE;
    float* mb = Ps + 64 * AT_STRIDE;

    int tid = threadIdx.x;
    int bh = blockIdx.y;
    int b = bh >> 3, h = bh & 7;
    int q0 = blockIdx.x * 64;
    const float scale = 0.125f;       // 1/sqrt(64)

    int lr  = tid >> 2;               // 0..63
    int lc0 = (tid & 3) * 4;          // 0,4,8,12

    // load Q tile once
    {
        const float* qbase = q + ((size_t)(b * SEQ + q0 + lr)) * DMODEL + h * HDIM;
        #pragma unroll
        for (int j = 0; j < 4; j++)
            *(float4*)&Qs[lr * AT_STRIDE + lc0 + j * 16] = *(const float4*)(qbase + lc0 + j * 16);
    }

    int ty = tid >> 4, tx = tid & 15;

    float m[4], l[4], acc[4][4];
    #pragma unroll
    for (int i = 0; i < 4; i++) {
        m[i] = -INFINITY; l[i] = 0.0f;
        #pragma unroll
        for (int j = 0; j < 4; j++) acc[i][j] = 0.0f;
    }

    for (int kt = 0; kt < SEQ / 64; kt++) {
        __syncthreads();
        {
            const float* kbase = k + ((size_t)(b * SEQ + kt * 64 + lr)) * DMODEL + h * HDIM;
            const float* vbase = v + ((size_t)(b * SEQ + kt * 64 + lr)) * DMODEL + h * HDIM;
            #pragma unroll
            for (int j = 0; j < 4; j++) {
                *(float4*)&Ks[lr * AT_STRIDE + lc0 + j * 16] = *(const float4*)(kbase + lc0 + j * 16);
                *(float4*)&Vs[lr * AT_STRIDE + lc0 + j * 16] = *(const float4*)(vbase + lc0 + j * 16);
            }
            if (tid < 64)
                mb[tid] = (mask[b * SEQ + kt * 64 + tid] != 0) ? 0.0f : -1e9f;
        }
        __syncthreads();

        // S = Q @ K^T
        float sv[4][4];
        #pragma unroll
        for (int i = 0; i < 4; i++)
            #pragma unroll
            for (int j = 0; j < 4; j++) sv[i][j] = 0.0f;

        #pragma unroll 4
        for (int kk = 0; kk < 16; kk++) {
            float4 a[4], bb[4];
            #pragma unroll
            for (int i = 0; i < 4; i++) a[i]  = *(float4*)&Qs[(ty * 4 + i) * AT_STRIDE + kk * 4];
            #pragma unroll
            for (int j = 0; j < 4; j++) bb[j] = *(float4*)&Ks[(tx * 4 + j) * AT_STRIDE + kk * 4];
            #pragma unroll
            for (int i = 0; i < 4; i++)
                #pragma unroll
                for (int j = 0; j < 4; j++)
                    sv[i][j] += a[i].x * bb[j].x + a[i].y * bb[j].y + a[i].z * bb[j].z + a[i].w * bb[j].w;
        }

        #pragma unroll
        for (int i = 0; i < 4; i++)
            #pragma unroll
            for (int j = 0; j < 4; j++)
                sv[i][j] = sv[i][j] * scale + mb[tx * 4 + j];

        // online softmax update (row reduce over the 16-thread tx group)
        #pragma unroll
        for (int i = 0; i < 4; i++) {
            float rmax = fmaxf(fmaxf(sv[i][0], sv[i][1]), fmaxf(sv[i][2], sv[i][3]));
            #pragma unroll
            for (int o = 8; o > 0; o >>= 1)
                rmax = fmaxf(rmax, __shfl_xor_sync(0xffffffffu, rmax, o));
            float mnew = fmaxf(m[i], rmax);
            float fac  = __expf(m[i] - mnew);
            float ps[4]; float rs = 0.0f;
            #pragma unroll
            for (int j = 0; j < 4; j++) { ps[j] = __expf(sv[i][j] - mnew); rs += ps[j]; }
            #pragma unroll
            for (int o = 8; o > 0; o >>= 1)
                rs += __shfl_xor_sync(0xffffffffu, rs, o);
            l[i] = l[i] * fac + rs;
            m[i] = mnew;
            #pragma unroll
            for (int j = 0; j < 4; j++) acc[i][j] *= fac;
            #pragma unroll
            for (int j = 0; j < 4; j++)
                Ps[(ty * 4 + i) * AT_STRIDE + tx * 4 + j] = ps[j];
        }
        __syncthreads();

        // O += P @ V
        #pragma unroll 4
        for (int c = 0; c < 64; c++) {
            float4 vv = *(float4*)&Vs[c * AT_STRIDE + tx * 4];
            #pragma unroll
            for (int i = 0; i < 4; i++) {
                float pv = Ps[(ty * 4 + i) * AT_STRIDE + c];
                acc[i][0] += pv * vv.x;
                acc[i][1] += pv * vv.y;
                acc[i][2] += pv * vv.z;
                acc[i][3] += pv * vv.w;
            }
        }
    }

    #pragma unroll
    for (int i = 0; i < 4; i++) {
        float inv = 1.0f / l[i];
        float4 o4;
        o4.x = acc[i][0] * inv; o4.y = acc[i][1] * inv;
        o4.z = acc[i][2] * inv; o4.w = acc[i][3] * inv;
        *(float4*)(out + ((size_t)(b * SEQ + q0 + ty * 4 + i)) * DMODEL + h * HDIM + tx * 4) = o4;
    }
}

// ---------------- host driver ----------------
extern "C" void kernel_launch(void* const* d_in, const int* in_sizes, int n_in,
                              void* d_out, int out_size)
{
    const float* x     = (const float*)d_in[0];
    const int*   mask  = (const int*)d_in[1];
    const float* Wq    = (const float*)d_in[2];
    const float* Wk    = (const float*)d_in[3];
    const float* Wv    = (const float*)d_in[4];
    const float* Wo    = (const float*)d_in[5];
    const float* ln1_g = (const float*)d_in[6];
    const float* ln1_b = (const float*)d_in[7];
    const float* ln2_g = (const float*)d_in[8];
    const float* ln2_b = (const float*)d_in[9];
    const float* W1    = (const float*)d_in[10];
    const float* b1    = (const float*)d_in[11];
    const float* W2    = (const float*)d_in[12];
    const float* b2    = (const float*)d_in[13];

    static float *px = nullptr, *ph, *pq, *pk, *pv, *pa, *pf;
    if (!px) {
        cudaGetSymbolAddress((void**)&ph, g_h);
        cudaGetSymbolAddress((void**)&pq, g_q);
        cudaGetSymbolAddress((void**)&pk, g_k);
        cudaGetSymbolAddress((void**)&pv, g_v);
        cudaGetSymbolAddress((void**)&pa, g_attn);
        cudaGetSymbolAddress((void**)&pf, g_ffn);
        cudaFuncSetAttribute(attn_kernel, cudaFuncAttributeMaxDynamicSharedMemorySize, ATT_SMEM);
        cudaGetSymbolAddress((void**)&px, g_x);   // last: acts as init flag
    }

    posenc_kernel<<<(MROWS * DMODEL + 255) / 256, 256>>>(x, px);

    dim3 gD(DMODEL / 128, MROWS / 128);     // 4 x 64
    dim3 gF(DFF / 128,    MROWS / 128);     // 16 x 64
    dim3 gA(SEQ / 64, BATCH * NHEAD);       // 16 x 64

    for (int l = 0; l < NLAYERS; l++) {
        const float* wq = Wq + (size_t)l * DMODEL * DMODEL;
        const float* wk = Wk + (size_t)l * DMODEL * DMODEL;
        const float* wv = Wv + (size_t)l * DMODEL * DMODEL;
        const float* wo = Wo + (size_t)l * DMODEL * DMODEL;
        const float* w1 = W1 + (size_t)l * DMODEL * DFF;
        const float* w2 = W2 + (size_t)l * DFF * DMODEL;

        ln_kernel<<<MROWS, 128>>>(px, ln1_g + l * DMODEL, ln1_b + l * DMODEL, ph);

        gemm128<0><<<gD, 256>>>(ph, wq, nullptr, nullptr, pq, DMODEL, DMODEL);
        gemm128<0><<<gD, 256>>>(ph, wk, nullptr, nullptr, pk, DMODEL, DMODEL);
        gemm128<0><<<gD, 256>>>(ph, wv, nullptr, nullptr, pv, DMODEL, DMODEL);

        attn_kernel<<<gA, 256, ATT_SMEM>>>(pq, pk, pv, mask, pa);

        gemm128<1><<<gD, 256>>>(pa, wo, nullptr, px, px, DMODEL, DMODEL);

        ln_kernel<<<MROWS, 128>>>(px, ln2_g + l * DMODEL, ln2_b + l * DMODEL, ph);

        gemm128<2><<<gF, 256>>>(ph, w1, b1 + (size_t)l * DFF, nullptr, pf, DMODEL, DFF);

        float* outp = (l == NLAYERS - 1) ? (float*)d_out : px;
        gemm128<3><<<gD, 256>>>(pf, w2, b2 + (size_t)l * DMODEL, px, outp, DFF, DMODEL);
    }
}

// round 5
// speedup vs baseline: 1.4157x; 1.4157x over previous
#include <cuda_runtime.h>
#include <cuda_bf16.h>
#include <math.h>
#include <stdint.h>

// ---------------- problem constants ----------------
#define NLAYERS 4
#define DMODEL  512
#define NHEAD   8
#define HDIM    64
#define DFF     2048
#define BATCH   8
#define SEQ     1024
#define MROWS   (BATCH*SEQ)          // 8192
#define LN_EPS  1e-3f

// per-layer weight element counts (transposed bf16 store)
#define WLAYER  3145728               // 4*512*512 + 2*512*2048
#define WT_ELEMS (NLAYERS*WLAYER)     // 12,582,912

// ---------------- device scratch (allocation-free) ----------------
__device__ float g_x   [MROWS*DMODEL];
__device__ float g_h   [MROWS*DMODEL];
__device__ float g_q   [MROWS*DMODEL];
__device__ float g_k   [MROWS*DMODEL];
__device__ float g_v   [MROWS*DMODEL];
__device__ float g_attn[MROWS*DMODEL];
__device__ float g_ffn [MROWS*DFF];
__device__ uint4 g_wth [WT_ELEMS/8];  // weights hi bf16, [N][K] transposed, 16B aligned
__device__ uint4 g_wtl [WT_ELEMS/8];  // weights lo bf16

extern __shared__ char dyn_smem[];

// ---------------- mma.sync helper (base sm_103 target OK) ----------------
__device__ __forceinline__ void mma16816(float* c, const uint32_t* a, uint32_t b0, uint32_t b1) {
    asm volatile(
        "mma.sync.aligned.m16n8k16.row.col.f32.bf16.bf16.f32 "
        "{%0,%1,%2,%3}, {%4,%5,%6,%7}, {%8,%9}, {%0,%1,%2,%3};"
        : "+f"(c[0]), "+f"(c[1]), "+f"(c[2]), "+f"(c[3])
        : "r"(a[0]), "r"(a[1]), "r"(a[2]), "r"(a[3]), "r"(b0), "r"(b1));
}

__device__ __forceinline__ uint32_t pack_bf16_hi(float x, float y) {
    __nv_bfloat16 hx = __float2bfloat16(x), hy = __float2bfloat16(y);
    return (uint32_t)__bfloat16_as_ushort(hx) | ((uint32_t)__bfloat16_as_ushort(hy) << 16);
}
__device__ __forceinline__ uint32_t pack_bf16_lo(float x, float y) {
    __nv_bfloat16 hx = __float2bfloat16(x), hy = __float2bfloat16(y);
    float lx = x - __bfloat162float(hx), ly = y - __bfloat162float(hy);
    __nv_bfloat16 bx = __float2bfloat16(lx), by = __float2bfloat16(ly);
    return (uint32_t)__bfloat16_as_ushort(bx) | ((uint32_t)__bfloat16_as_ushort(by) << 16);
}

// ---------------- positional encoding + add ----------------
__global__ void posenc_kernel(const float* __restrict__ x, float* __restrict__ out) {
    int idx = blockIdx.x * 256 + threadIdx.x;
    if (idx >= MROWS * DMODEL) return;
    int d = idx & (DMODEL - 1);
    int s = (idx / DMODEL) & (SEQ - 1);
    const int half = DMODEL / 2;
    float val;
    if (d < half) {
        float ang = (float)s * expf(-logf(10000.0f) * (2.0f * (float)d / (float)DMODEL));
        val = sinf(ang);
    } else {
        float j = (float)(d - half);
        float ang = (float)s * expf(-logf(10000.0f) * (2.0f * j / (float)DMODEL));
        val = cosf(ang);
    }
    out[idx] = x[idx] + val;
}

// ---------------- layernorm ----------------
__global__ void ln_kernel(const float* __restrict__ x, const float* __restrict__ gamma,
                          const float* __restrict__ beta, float* __restrict__ out) {
    int row = blockIdx.x;
    int t = threadIdx.x;
    const float4* xr = (const float4*)(x + (size_t)row * DMODEL);
    float4 v = xr[t];

    __shared__ float red1[4];
    __shared__ float red2[4];

    float s = v.x + v.y + v.z + v.w;
    #pragma unroll
    for (int o = 16; o > 0; o >>= 1) s += __shfl_xor_sync(0xffffffffu, s, o);
    if ((t & 31) == 0) red1[t >> 5] = s;
    __syncthreads();
    float mean = (red1[0] + red1[1] + red1[2] + red1[3]) * (1.0f / DMODEL);

    float dx = v.x - mean, dy = v.y - mean, dz = v.z - mean, dw = v.w - mean;
    float s2 = dx*dx + dy*dy + dz*dz + dw*dw;
    #pragma unroll
    for (int o = 16; o > 0; o >>= 1) s2 += __shfl_xor_sync(0xffffffffu, s2, o);
    if ((t & 31) == 0) red2[t >> 5] = s2;
    __syncthreads();
    float var = (red2[0] + red2[1] + red2[2] + red2[3]) * (1.0f / DMODEL);
    float rs = rsqrtf(var + LN_EPS);

    float4 g4 = ((const float4*)gamma)[t];
    float4 b4 = ((const float4*)beta)[t];
    float4 o4;
    o4.x = dx * rs * g4.x + b4.x;
    o4.y = dy * rs * g4.y + b4.y;
    o4.z = dz * rs * g4.z + b4.z;
    o4.w = dw * rs * g4.w + b4.w;
    ((float4*)(out + (size_t)row * DMODEL))[t] = o4;
}

// ---------------- weight convert+transpose: fp32 [K][N] -> bf16 hi/lo [N][K] ----------------
__global__ void wconv_kernel(const float* __restrict__ W,
                             __nv_bfloat16* __restrict__ Oh, __nv_bfloat16* __restrict__ Ol,
                             int K, int N) {
    __shared__ float tile[32][33];
    int tn = blockIdx.x * 32, tk = blockIdx.y * 32;
    int tx = threadIdx.x, ty = threadIdx.y;    // (32, 8)
    #pragma unroll
    for (int i = 0; i < 4; i++)
        tile[ty + i * 8][tx] = W[(size_t)(tk + ty + i * 8) * N + tn + tx];
    __syncthreads();
    #pragma unroll
    for (int i = 0; i < 4; i++) {
        int nl = ty + i * 8;
        float v = tile[tx][nl];                 // [k_local][n_local]
        __nv_bfloat16 h = __float2bfloat16(v);
        __nv_bfloat16 l = __float2bfloat16(v - __bfloat162float(h));
        size_t o = (size_t)(tn + nl) * K + tk + tx;
        Oh[o] = h;
        Ol[o] = l;
    }
}

// ---------------- bf16x3 mma.sync GEMM: C[128,128] tile, BK=32 ----------------
// C = A[M,K](fp32) @ W[K,N] with W given as hi/lo bf16 transposed [N][K].
// EPI: 0 plain, 1 +res, 2 relu(+bias), 3 +bias+res
#define BKP 20   // u32 row stride (40 bf16 = 80B): (g*20+t)%32 hits all banks

template<int EPI>
__global__ __launch_bounds__(256) void gemm_mma(
    const float* __restrict__ A,
    const __nv_bfloat16* __restrict__ Wh, const __nv_bfloat16* __restrict__ Wl,
    const float* __restrict__ bias, const float* __restrict__ res,
    float* __restrict__ C, int K, int N)
{
    __shared__ uint32_t Ah[128 * BKP];
    __shared__ uint32_t Al[128 * BKP];
    __shared__ uint32_t Bh[128 * BKP];
    __shared__ uint32_t Bl[128 * BKP];

    int tid = threadIdx.x;
    int lane = tid & 31, wid = tid >> 5;
    int wm = wid >> 1, wn = wid & 1;           // warp grid 4x2
    int m0 = blockIdx.y * 128, n0 = blockIdx.x * 128;
    int g = lane >> 2, t = lane & 3;

    float c[2][8][4];
    #pragma unroll
    for (int mt = 0; mt < 2; mt++)
        #pragma unroll
        for (int nt = 0; nt < 8; nt++)
            #pragma unroll
            for (int e = 0; e < 4; e++) c[mt][nt][e] = 0.0f;

    int arow = tid >> 1;                        // 0..127
    int ahalf = tid & 1;                        // which 16-float half of the 32-k chunk

    for (int kb = 0; kb < K; kb += 32) {
        // ---- A tile: fp32 [128][32] -> hi/lo bf16x2 smem ----
        const float* ap = A + (size_t)(m0 + arow) * K + kb + ahalf * 16;
        #pragma unroll
        for (int p = 0; p < 4; p++) {
            float4 v = *(const float4*)(ap + p * 4);
            int idx = arow * BKP + ahalf * 8 + p * 2;
            Ah[idx]     = pack_bf16_hi(v.x, v.y);
            Ah[idx + 1] = pack_bf16_hi(v.z, v.w);
            Al[idx]     = pack_bf16_lo(v.x, v.y);
            Al[idx + 1] = pack_bf16_lo(v.z, v.w);
        }
        // ---- B tile: bf16 [N=128 rows][32 k] straight copy (pre-transposed) ----
        {
            const uint4* bh = (const uint4*)(Wh + (size_t)(n0 + arow) * K + kb);
            const uint4* bl = (const uint4*)(Wl + (size_t)(n0 + arow) * K + kb);
            #pragma unroll
            for (int p = 0; p < 2; p++) {
                int q = ahalf * 2 + p;          // 0..3 (uint4 within row)
                *(uint4*)&Bh[arow * BKP + q * 4] = bh[q];
                *(uint4*)&Bl[arow * BKP + q * 4] = bl[q];
            }
        }
        __syncthreads();

        // ---- compute: 2 k16 steps ----
        #pragma unroll
        for (int s = 0; s < 2; s++) {
            uint32_t ahf[2][4], alf[2][4];
            #pragma unroll
            for (int mt = 0; mt < 2; mt++) {
                int base = (wm * 32 + mt * 16 + g) * BKP + s * 8 + t;
                ahf[mt][0] = Ah[base];
                ahf[mt][1] = Ah[base + 8 * BKP];
                ahf[mt][2] = Ah[base + 4];
                ahf[mt][3] = Ah[base + 8 * BKP + 4];
                alf[mt][0] = Al[base];
                alf[mt][1] = Al[base + 8 * BKP];
                alf[mt][2] = Al[base + 4];
                alf[mt][3] = Al[base + 8 * BKP + 4];
            }
            #pragma unroll
            for (int nt = 0; nt < 8; nt++) {
                int bbase = (wn * 64 + nt * 8 + g) * BKP + s * 8 + t;
                uint32_t bh0 = Bh[bbase], bh1 = Bh[bbase + 4];
                uint32_t bl0 = Bl[bbase], bl1 = Bl[bbase + 4];
                #pragma unroll
                for (int mt = 0; mt < 2; mt++) {
                    mma16816(c[mt][nt], ahf[mt], bh0, bh1);
                    mma16816(c[mt][nt], alf[mt], bh0, bh1);
                    mma16816(c[mt][nt], ahf[mt], bl0, bl1);
                }
            }
        }
        __syncthreads();
    }

    // ---- epilogue ----
    #pragma unroll
    for (int mt = 0; mt < 2; mt++) {
        #pragma unroll
        for (int nt = 0; nt < 8; nt++) {
            int row = m0 + wm * 32 + mt * 16 + g;
            int col = n0 + wn * 64 + nt * 8 + t * 2;
            float2 v1 = make_float2(c[mt][nt][0], c[mt][nt][1]);
            float2 v2 = make_float2(c[mt][nt][2], c[mt][nt][3]);
            if (EPI == 2 || EPI == 3) {
                float2 bb = *(const float2*)(bias + col);
                v1.x += bb.x; v1.y += bb.y;
                v2.x += bb.x; v2.y += bb.y;
            }
            if (EPI == 2) {
                v1.x = fmaxf(v1.x, 0.0f); v1.y = fmaxf(v1.y, 0.0f);
                v2.x = fmaxf(v2.x, 0.0f); v2.y = fmaxf(v2.y, 0.0f);
            }
            if (EPI == 1 || EPI == 3) {
                float2 r1 = *(const float2*)(res + (size_t)row * N + col);
                float2 r2 = *(const float2*)(res + (size_t)(row + 8) * N + col);
                v1.x += r1.x; v1.y += r1.y;
                v2.x += r2.x; v2.y += r2.y;
            }
            *(float2*)(C + (size_t)row * N + col) = v1;
            *(float2*)(C + (size_t)(row + 8) * N + col) = v2;
        }
    }
}

// ---------------- flash attention (SIMT) ----------------
#define AT_STRIDE 68
#define ATT_SMEM ((4 * 64 * AT_STRIDE + 64) * (int)sizeof(float))

__global__ __launch_bounds__(256) void attn_kernel(
    const float* __restrict__ q, const float* __restrict__ k,
    const float* __restrict__ v, const int* __restrict__ mask,
    float* __restrict__ out)
{
    float* smem = (float*)dyn_smem;
    float* Qs = smem;
    float* Ks = Qs + 64 * AT_STRIDE;
    float* Vs = Ks + 64 * AT_STRIDE;
    float* Ps = Vs + 64 * AT_STRIDE;
    float* mb = Ps + 64 * AT_STRIDE;

    int tid = threadIdx.x;
    int bh = blockIdx.y;
    int b = bh >> 3, h = bh & 7;
    int q0 = blockIdx.x * 64;
    const float scale = 0.125f;

    int lr  = tid >> 2;
    int lc0 = (tid & 3) * 4;

    {
        const float* qbase = q + ((size_t)(b * SEQ + q0 + lr)) * DMODEL + h * HDIM;
        #pragma unroll
        for (int j = 0; j < 4; j++)
            *(float4*)&Qs[lr * AT_STRIDE + lc0 + j * 16] = *(const float4*)(qbase + lc0 + j * 16);
    }

    int ty = tid >> 4, tx = tid & 15;

    float m[4], l[4], acc[4][4];
    #pragma unroll
    for (int i = 0; i < 4; i++) {
        m[i] = -INFINITY; l[i] = 0.0f;
        #pragma unroll
        for (int j = 0; j < 4; j++) acc[i][j] = 0.0f;
    }

    for (int kt = 0; kt < SEQ / 64; kt++) {
        __syncthreads();
        {
            const float* kbase = k + ((size_t)(b * SEQ + kt * 64 + lr)) * DMODEL + h * HDIM;
            const float* vbase = v + ((size_t)(b * SEQ + kt * 64 + lr)) * DMODEL + h * HDIM;
            #pragma unroll
            for (int j = 0; j < 4; j++) {
                *(float4*)&Ks[lr * AT_STRIDE + lc0 + j * 16] = *(const float4*)(kbase + lc0 + j * 16);
                *(float4*)&Vs[lr * AT_STRIDE + lc0 + j * 16] = *(const float4*)(vbase + lc0 + j * 16);
            }
            if (tid < 64)
                mb[tid] = (mask[b * SEQ + kt * 64 + tid] != 0) ? 0.0f : -1e9f;
        }
        __syncthreads();

        float sv[4][4];
        #pragma unroll
        for (int i = 0; i < 4; i++)
            #pragma unroll
            for (int j = 0; j < 4; j++) sv[i][j] = 0.0f;

        #pragma unroll 4
        for (int kk = 0; kk < 16; kk++) {
            float4 a[4], bb[4];
            #pragma unroll
            for (int i = 0; i < 4; i++) a[i]  = *(float4*)&Qs[(ty * 4 + i) * AT_STRIDE + kk * 4];
            #pragma unroll
            for (int j = 0; j < 4; j++) bb[j] = *(float4*)&Ks[(tx * 4 + j) * AT_STRIDE + kk * 4];
            #pragma unroll
            for (int i = 0; i < 4; i++)
                #pragma unroll
                for (int j = 0; j < 4; j++)
                    sv[i][j] += a[i].x * bb[j].x + a[i].y * bb[j].y + a[i].z * bb[j].z + a[i].w * bb[j].w;
        }

        #pragma unroll
        for (int i = 0; i < 4; i++)
            #pragma unroll
            for (int j = 0; j < 4; j++)
                sv[i][j] = sv[i][j] * scale + mb[tx * 4 + j];

        #pragma unroll
        for (int i = 0; i < 4; i++) {
            float rmax = fmaxf(fmaxf(sv[i][0], sv[i][1]), fmaxf(sv[i][2], sv[i][3]));
            #pragma unroll
            for (int o = 8; o > 0; o >>= 1)
                rmax = fmaxf(rmax, __shfl_xor_sync(0xffffffffu, rmax, o));
            float mnew = fmaxf(m[i], rmax);
            float fac  = __expf(m[i] - mnew);
            float ps[4]; float rs = 0.0f;
            #pragma unroll
            for (int j = 0; j < 4; j++) { ps[j] = __expf(sv[i][j] - mnew); rs += ps[j]; }
            #pragma unroll
            for (int o = 8; o > 0; o >>= 1)
                rs += __shfl_xor_sync(0xffffffffu, rs, o);
            l[i] = l[i] * fac + rs;
            m[i] = mnew;
            #pragma unroll
            for (int j = 0; j < 4; j++) acc[i][j] *= fac;
            #pragma unroll
            for (int j = 0; j < 4; j++)
                Ps[(ty * 4 + i) * AT_STRIDE + tx * 4 + j] = ps[j];
        }
        __syncthreads();

        #pragma unroll 4
        for (int c = 0; c < 64; c++) {
            float4 vv = *(float4*)&Vs[c * AT_STRIDE + tx * 4];
            #pragma unroll
            for (int i = 0; i < 4; i++) {
                float pv = Ps[(ty * 4 + i) * AT_STRIDE + c];
                acc[i][0] += pv * vv.x;
                acc[i][1] += pv * vv.y;
                acc[i][2] += pv * vv.z;
                acc[i][3] += pv * vv.w;
            }
        }
    }

    #pragma unroll
    for (int i = 0; i < 4; i++) {
        float inv = 1.0f / l[i];
        float4 o4;
        o4.x = acc[i][0] * inv; o4.y = acc[i][1] * inv;
        o4.z = acc[i][2] * inv; o4.w = acc[i][3] * inv;
        *(float4*)(out + ((size_t)(b * SEQ + q0 + ty * 4 + i)) * DMODEL + h * HDIM + tx * 4) = o4;
    }
}

// ---------------- host driver ----------------
extern "C" void kernel_launch(void* const* d_in, const int* in_sizes, int n_in,
                              void* d_out, int out_size)
{
    const float* x     = (const float*)d_in[0];
    const int*   mask  = (const int*)d_in[1];
    const float* Wq    = (const float*)d_in[2];
    const float* Wk    = (const float*)d_in[3];
    const float* Wv    = (const float*)d_in[4];
    const float* Wo    = (const float*)d_in[5];
    const float* ln1_g = (const float*)d_in[6];
    const float* ln1_b = (const float*)d_in[7];
    const float* ln2_g = (const float*)d_in[8];
    const float* ln2_b = (const float*)d_in[9];
    const float* W1    = (const float*)d_in[10];
    const float* b1    = (const float*)d_in[11];
    const float* W2    = (const float*)d_in[12];
    const float* b2    = (const float*)d_in[13];

    static float *px = nullptr, *ph, *pq, *pk, *pv, *pa, *pf;
    static __nv_bfloat16 *pwh, *pwl;
    if (!px) {
        cudaGetSymbolAddress((void**)&ph, g_h);
        cudaGetSymbolAddress((void**)&pq, g_q);
        cudaGetSymbolAddress((void**)&pk, g_k);
        cudaGetSymbolAddress((void**)&pv, g_v);
        cudaGetSymbolAddress((void**)&pa, g_attn);
        cudaGetSymbolAddress((void**)&pf, g_ffn);
        cudaGetSymbolAddress((void**)&pwh, g_wth);
        cudaGetSymbolAddress((void**)&pwl, g_wtl);
        cudaFuncSetAttribute(attn_kernel, cudaFuncAttributeMaxDynamicSharedMemorySize, ATT_SMEM);
        cudaGetSymbolAddress((void**)&px, g_x);   // last: acts as init flag
    }

    // ---- weight convert+transpose (runs in graph; ~30us total) ----
    {
        dim3 blk(32, 8);
        for (int l = 0; l < NLAYERS; l++) {
            size_t base = (size_t)l * WLAYER;
            dim3 gDD(DMODEL / 32, DMODEL / 32);
            wconv_kernel<<<gDD, blk>>>(Wq + (size_t)l * DMODEL * DMODEL, pwh + base,           pwl + base,           DMODEL, DMODEL);
            wconv_kernel<<<gDD, blk>>>(Wk + (size_t)l * DMODEL * DMODEL, pwh + base + 262144,  pwl + base + 262144,  DMODEL, DMODEL);
            wconv_kernel<<<gDD, blk>>>(Wv + (size_t)l * DMODEL * DMODEL, pwh + base + 524288,  pwl + base + 524288,  DMODEL, DMODEL);
            wconv_kernel<<<gDD, blk>>>(Wo + (size_t)l * DMODEL * DMODEL, pwh + base + 786432,  pwl + base + 786432,  DMODEL, DMODEL);
            dim3 g1(DFF / 32, DMODEL / 32);     // W1: K=512, N=2048 -> out [2048][512]
            wconv_kernel<<<g1, blk>>>(W1 + (size_t)l * DMODEL * DFF,     pwh + base + 1048576, pwl + base + 1048576, DMODEL, DFF);
            dim3 g2(DMODEL / 32, DFF / 32);     // W2: K=2048, N=512 -> out [512][2048]
            wconv_kernel<<<g2, blk>>>(W2 + (size_t)l * DFF * DMODEL,     pwh + base + 2097152, pwl + base + 2097152, DFF, DMODEL);
        }
    }

    posenc_kernel<<<(MROWS * DMODEL + 255) / 256, 256>>>(x, px);

    dim3 gD(DMODEL / 128, MROWS / 128);     // 4 x 64
    dim3 gF(DFF / 128,    MROWS / 128);     // 16 x 64
    dim3 gA(SEQ / 64, BATCH * NHEAD);       // 16 x 64

    for (int l = 0; l < NLAYERS; l++) {
        size_t base = (size_t)l * WLAYER;
        const __nv_bfloat16 *qh = pwh + base,           *ql = pwl + base;
        const __nv_bfloat16 *kh = pwh + base + 262144,  *kl = pwl + base + 262144;
        const __nv_bfloat16 *vh = pwh + base + 524288,  *vl = pwl + base + 524288;
        const __nv_bfloat16 *oh = pwh + base + 786432,  *ol = pwl + base + 786432;
        const __nv_bfloat16 *f1h = pwh + base + 1048576, *f1l = pwl + base + 1048576;
        const __nv_bfloat16 *f2h = pwh + base + 2097152, *f2l = pwl + base + 2097152;

        ln_kernel<<<MROWS, 128>>>(px, ln1_g + l * DMODEL, ln1_b + l * DMODEL, ph);

        gemm_mma<0><<<gD, 256>>>(ph, qh, ql, nullptr, nullptr, pq, DMODEL, DMODEL);
        gemm_mma<0><<<gD, 256>>>(ph, kh, kl, nullptr, nullptr, pk, DMODEL, DMODEL);
        gemm_mma<0><<<gD, 256>>>(ph, vh, vl, nullptr, nullptr, pv, DMODEL, DMODEL);

        attn_kernel<<<gA, 256, ATT_SMEM>>>(pq, pk, pv, mask, pa);

        gemm_mma<1><<<gD, 256>>>(pa, oh, ol, nullptr, px, px, DMODEL, DMODEL);

        ln_kernel<<<MROWS, 128>>>(px, ln2_g + l * DMODEL, ln2_b + l * DMODEL, ph);

        gemm_mma<2><<<gF, 256>>>(ph, f1h, f1l, b1 + (size_t)l * DFF, nullptr, pf, DMODEL, DFF);

        float* outp = (l == NLAYERS - 1) ? (float*)d_out : px;
        gemm_mma<3><<<gD, 256>>>(pf, f2h, f2l, b2 + (size_t)l * DMODEL, px, outp, DFF, DMODEL);
    }
}

// round 6
// speedup vs baseline: 1.4530x; 1.0263x over previous
#include <cuda_runtime.h>
#include <cuda_bf16.h>
#include <math.h>
#include <stdint.h>

// ---------------- problem constants ----------------
#define NLAYERS 4
#define DMODEL  512
#define NHEAD   8
#define HDIM    64
#define DFF     2048
#define BATCH   8
#define SEQ     1024
#define MROWS   (BATCH*SEQ)          // 8192
#define LN_EPS  1e-3f
#define QKVN    1536

#define WLAYER  3145728               // 4*512*512 + 2*512*2048
#define WT_ELEMS (NLAYERS*WLAYER)

// ---------------- device scratch (allocation-free) ----------------
__device__ float g_x   [MROWS*DMODEL];
__device__ float g_qkv [MROWS*QKVN];
__device__ __nv_bfloat16 g_lnh[MROWS*DMODEL];
__device__ __nv_bfloat16 g_lnl[MROWS*DMODEL];
__device__ __nv_bfloat16 g_pah[MROWS*DMODEL];
__device__ __nv_bfloat16 g_pal[MROWS*DMODEL];
__device__ __nv_bfloat16 g_pfh[MROWS*DFF];
__device__ __nv_bfloat16 g_pfl[MROWS*DFF];
__device__ uint4 g_wth [WT_ELEMS/8];
__device__ uint4 g_wtl [WT_ELEMS/8];

extern __shared__ char dyn_smem[];

// ---------------- helpers ----------------
__device__ __forceinline__ uint32_t smem_u32(const void* p) {
    uint32_t a;
    asm("{ .reg .u64 t; cvta.to.shared.u64 t, %1; cvt.u32.u64 %0, t; }" : "=r"(a) : "l"(p));
    return a;
}
__device__ __forceinline__ void mma16816(float* c, const uint32_t* a, uint32_t b0, uint32_t b1) {
    asm volatile(
        "mma.sync.aligned.m16n8k16.row.col.f32.bf16.bf16.f32 "
        "{%0,%1,%2,%3}, {%4,%5,%6,%7}, {%8,%9}, {%0,%1,%2,%3};"
        : "+f"(c[0]), "+f"(c[1]), "+f"(c[2]), "+f"(c[3])
        : "r"(a[0]), "r"(a[1]), "r"(a[2]), "r"(a[3]), "r"(b0), "r"(b1));
}
__device__ __forceinline__ void cpasync16(uint32_t saddr, const void* gptr) {
    asm volatile("cp.async.cg.shared.global [%0], [%1], 16;" :: "r"(saddr), "l"(gptr));
}
__device__ __forceinline__ void cp_commit() { asm volatile("cp.async.commit_group;" ::: "memory"); }
__device__ __forceinline__ void cp_wait1()  { asm volatile("cp.async.wait_group 1;"  ::: "memory"); }
__device__ __forceinline__ void cp_wait0()  { asm volatile("cp.async.wait_group 0;"  ::: "memory"); }

__device__ __forceinline__ void split_bf16(float v, __nv_bfloat16& h, __nv_bfloat16& l) {
    h = __float2bfloat16(v);
    l = __float2bfloat16(v - __bfloat162float(h));
}
__device__ __forceinline__ uint32_t pack2(__nv_bfloat16 a, __nv_bfloat16 b) {
    return (uint32_t)__bfloat16_as_ushort(a) | ((uint32_t)__bfloat16_as_ushort(b) << 16);
}

// ---------------- positional encoding ----------------
__global__ void posenc_kernel(const float* __restrict__ x, float* __restrict__ out) {
    int idx = blockIdx.x * 256 + threadIdx.x;
    if (idx >= MROWS * DMODEL) return;
    int d = idx & (DMODEL - 1);
    int s = (idx / DMODEL) & (SEQ - 1);
    const int half = DMODEL / 2;
    float val;
    if (d < half) {
        float ang = (float)s * expf(-logf(10000.0f) * (2.0f * (float)d / (float)DMODEL));
        val = sinf(ang);
    } else {
        float j = (float)(d - half);
        float ang = (float)s * expf(-logf(10000.0f) * (2.0f * j / (float)DMODEL));
        val = cosf(ang);
    }
    out[idx] = x[idx] + val;
}

// ---------------- layernorm -> bf16 hi/lo ----------------
__global__ void ln_kernel(const float* __restrict__ x, const float* __restrict__ gamma,
                          const float* __restrict__ beta,
                          __nv_bfloat16* __restrict__ oh, __nv_bfloat16* __restrict__ ol) {
    int row = blockIdx.x;
    int t = threadIdx.x;
    const float4* xr = (const float4*)(x + (size_t)row * DMODEL);
    float4 v = xr[t];

    __shared__ float red1[4];
    __shared__ float red2[4];

    float s = v.x + v.y + v.z + v.w;
    #pragma unroll
    for (int o = 16; o > 0; o >>= 1) s += __shfl_xor_sync(0xffffffffu, s, o);
    if ((t & 31) == 0) red1[t >> 5] = s;
    __syncthreads();
    float mean = (red1[0] + red1[1] + red1[2] + red1[3]) * (1.0f / DMODEL);

    float dx = v.x - mean, dy = v.y - mean, dz = v.z - mean, dw = v.w - mean;
    float s2 = dx*dx + dy*dy + dz*dz + dw*dw;
    #pragma unroll
    for (int o = 16; o > 0; o >>= 1) s2 += __shfl_xor_sync(0xffffffffu, s2, o);
    if ((t & 31) == 0) red2[t >> 5] = s2;
    __syncthreads();
    float var = (red2[0] + red2[1] + red2[2] + red2[3]) * (1.0f / DMODEL);
    float rs = rsqrtf(var + LN_EPS);

    float4 g4 = ((const float4*)gamma)[t];
    float4 b4 = ((const float4*)beta)[t];
    float o0 = dx * rs * g4.x + b4.x;
    float o1 = dy * rs * g4.y + b4.y;
    float o2 = dz * rs * g4.z + b4.z;
    float o3 = dw * rs * g4.w + b4.w;
    __nv_bfloat16 h0,h1,h2,h3,l0,l1,l2,l3;
    split_bf16(o0,h0,l0); split_bf16(o1,h1,l1); split_bf16(o2,h2,l2); split_bf16(o3,h3,l3);
    uint2 hp = make_uint2(pack2(h0,h1), pack2(h2,h3));
    uint2 lp = make_uint2(pack2(l0,l1), pack2(l2,l3));
    *(uint2*)(oh + (size_t)row * DMODEL + t * 4) = hp;
    *(uint2*)(ol + (size_t)row * DMODEL + t * 4) = lp;
}

// ---------------- weight convert+transpose ----------------
__global__ void wconv_kernel(const float* __restrict__ W,
                             __nv_bfloat16* __restrict__ Oh, __nv_bfloat16* __restrict__ Ol,
                             int K, int N) {
    __shared__ float tile[32][33];
    int tn = blockIdx.x * 32, tk = blockIdx.y * 32;
    int tx = threadIdx.x, ty = threadIdx.y;
    #pragma unroll
    for (int i = 0; i < 4; i++)
        tile[ty + i * 8][tx] = W[(size_t)(tk + ty + i * 8) * N + tn + tx];
    __syncthreads();
    #pragma unroll
    for (int i = 0; i < 4; i++) {
        int nl = ty + i * 8;
        float v = tile[tx][nl];
        __nv_bfloat16 h, l;
        split_bf16(v, h, l);
        size_t o = (size_t)(tn + nl) * K + tk + tx;
        Oh[o] = h;
        Ol[o] = l;
    }
}

// ---------------- pipelined bf16x3 mma GEMM ----------------
// A given pre-split bf16 hi/lo [M][K]; W pre-split bf16 hi/lo [N][K].
// EPI: 0 plain, 1 +res, 2 relu(+bias), 3 +bias+res
// OUTF32: write Cf fp32;  OUTBF16: write Ch/Cl bf16 split
#define BKP 20
#define ARR_STRIDE (128 * BKP)                 // u32 per array
#define STAGE_BYTES (4 * ARR_STRIDE * 4)       // 40960
#define GEMM_SMEM2 (2 * STAGE_BYTES)           // 81920

template<int EPI, int OUTF32, int OUTBF16>
__global__ __launch_bounds__(256) void gemm_pipe(
    const __nv_bfloat16* __restrict__ Ah, const __nv_bfloat16* __restrict__ Al,
    const __nv_bfloat16* __restrict__ Wh, const __nv_bfloat16* __restrict__ Wl,
    const float* __restrict__ bias, const float* __restrict__ res,
    float* __restrict__ Cf, __nv_bfloat16* __restrict__ Ch, __nv_bfloat16* __restrict__ Cl,
    int K, int N)
{
    uint32_t sbase = smem_u32(dyn_smem);
    int tid = threadIdx.x;
    int lane = tid & 31, wid = tid >> 5;
    int wm = wid >> 1, wn = wid & 1;
    int m0 = blockIdx.y * 128, n0 = blockIdx.x * 128;
    int g = lane >> 2, t = lane & 3;

    int lrow = tid >> 1;             // 0..127
    int lhalf = tid & 1;             // chunk pair selector

    const __nv_bfloat16* agh = Ah + (size_t)(m0 + lrow) * K;
    const __nv_bfloat16* agl = Al + (size_t)(m0 + lrow) * K;
    const __nv_bfloat16* bgh = Wh + (size_t)(n0 + lrow) * K;
    const __nv_bfloat16* bgl = Wl + (size_t)(n0 + lrow) * K;
    uint32_t srow = sbase + (uint32_t)(lrow * BKP) * 4;

    auto issue_load = [&](int kb, int st) {
        uint32_t so = srow + (uint32_t)st * STAGE_BYTES;
        #pragma unroll
        for (int p = 0; p < 2; p++) {
            int q = lhalf * 2 + p;               // 16B chunk 0..3
            int ge = kb + q * 8;                  // gmem element offset
            uint32_t sb2 = so + (uint32_t)(q * 16);
            cpasync16(sb2,                          agh + ge);
            cpasync16(sb2 + ARR_STRIDE * 4,         agl + ge);
            cpasync16(sb2 + 2 * ARR_STRIDE * 4,     bgh + ge);
            cpasync16(sb2 + 3 * ARR_STRIDE * 4,     bgl + ge);
        }
        cp_commit();
    };

    float c[2][8][4];
    #pragma unroll
    for (int mt = 0; mt < 2; mt++)
        #pragma unroll
        for (int nt = 0; nt < 8; nt++)
            #pragma unroll
            for (int e = 0; e < 4; e++) c[mt][nt][e] = 0.0f;

    const int nkb = K >> 5;
    issue_load(0, 0);

    for (int kb = 0; kb < nkb; kb++) {
        int st = kb & 1;
        if (kb + 1 < nkb) issue_load((kb + 1) << 5, st ^ 1);
        if (kb + 1 < nkb) cp_wait1(); else cp_wait0();
        __syncthreads();

        uint32_t* As_h = (uint32_t*)(dyn_smem + st * STAGE_BYTES);
        uint32_t* As_l = As_h + ARR_STRIDE;
        uint32_t* Bs_h = As_h + 2 * ARR_STRIDE;
        uint32_t* Bs_l = As_h + 3 * ARR_STRIDE;

        #pragma unroll
        for (int s = 0; s < 2; s++) {
            uint32_t ahf[2][4], alf[2][4];
            #pragma unroll
            for (int mt = 0; mt < 2; mt++) {
                int base = (wm * 32 + mt * 16 + g) * BKP + s * 8 + t;
                ahf[mt][0] = As_h[base];
                ahf[mt][1] = As_h[base + 8 * BKP];
                ahf[mt][2] = As_h[base + 4];
                ahf[mt][3] = As_h[base + 8 * BKP + 4];
                alf[mt][0] = As_l[base];
                alf[mt][1] = As_l[base + 8 * BKP];
                alf[mt][2] = As_l[base + 4];
                alf[mt][3] = As_l[base + 8 * BKP + 4];
            }
            #pragma unroll
            for (int nt = 0; nt < 8; nt++) {
                int bbase = (wn * 64 + nt * 8 + g) * BKP + s * 8 + t;
                uint32_t bh0 = Bs_h[bbase], bh1 = Bs_h[bbase + 4];
                uint32_t bl0 = Bs_l[bbase], bl1 = Bs_l[bbase + 4];
                #pragma unroll
                for (int mt = 0; mt < 2; mt++) {
                    mma16816(c[mt][nt], ahf[mt], bh0, bh1);
                    mma16816(c[mt][nt], alf[mt], bh0, bh1);
                    mma16816(c[mt][nt], ahf[mt], bl0, bl1);
                }
            }
        }
        __syncthreads();
    }

    // ---- epilogue ----
    #pragma unroll
    for (int mt = 0; mt < 2; mt++) {
        #pragma unroll
        for (int nt = 0; nt < 8; nt++) {
            int row = m0 + wm * 32 + mt * 16 + g;
            int col = n0 + wn * 64 + nt * 8 + t * 2;
            float2 v1 = make_float2(c[mt][nt][0], c[mt][nt][1]);
            float2 v2 = make_float2(c[mt][nt][2], c[mt][nt][3]);
            if (EPI == 2 || EPI == 3) {
                float2 bb = *(const float2*)(bias + col);
                v1.x += bb.x; v1.y += bb.y;
                v2.x += bb.x; v2.y += bb.y;
            }
            if (EPI == 2) {
                v1.x = fmaxf(v1.x, 0.0f); v1.y = fmaxf(v1.y, 0.0f);
                v2.x = fmaxf(v2.x, 0.0f); v2.y = fmaxf(v2.y, 0.0f);
            }
            if (EPI == 1 || EPI == 3) {
                float2 r1 = *(const float2*)(res + (size_t)row * N + col);
                float2 r2 = *(const float2*)(res + (size_t)(row + 8) * N + col);
                v1.x += r1.x; v1.y += r1.y;
                v2.x += r2.x; v2.y += r2.y;
            }
            if (OUTF32) {
                *(float2*)(Cf + (size_t)row * N + col) = v1;
                *(float2*)(Cf + (size_t)(row + 8) * N + col) = v2;
            }
            if (OUTBF16) {
                __nv_bfloat16 h0,h1,l0,l1;
                split_bf16(v1.x, h0, l0); split_bf16(v1.y, h1, l1);
                *(uint32_t*)(Ch + (size_t)row * N + col) = pack2(h0, h1);
                *(uint32_t*)(Cl + (size_t)row * N + col) = pack2(l0, l1);
                split_bf16(v2.x, h0, l0); split_bf16(v2.y, h1, l1);
                *(uint32_t*)(Ch + (size_t)(row + 8) * N + col) = pack2(h0, h1);
                *(uint32_t*)(Cl + (size_t)(row + 8) * N + col) = pack2(l0, l1);
            }
        }
    }
}

// ---------------- flash attention (SIMT, qkv fused input, bf16 pair out) ----------------
#define AT_STRIDE 68
#define ATT_SMEM ((4 * 64 * AT_STRIDE + 64) * (int)sizeof(float))

__global__ __launch_bounds__(256) void attn_kernel(
    const float* __restrict__ qkv, const int* __restrict__ mask,
    __nv_bfloat16* __restrict__ oh, __nv_bfloat16* __restrict__ ol)
{
    float* smem = (float*)dyn_smem;
    float* Qs = smem;
    float* Ks = Qs + 64 * AT_STRIDE;
    float* Vs = Ks + 64 * AT_STRIDE;
    float* Ps = Vs + 64 * AT_STRIDE;
    float* mb = Ps + 64 * AT_STRIDE;

    int tid = threadIdx.x;
    int bh = blockIdx.y;
    int b = bh >> 3, h = bh & 7;
    int q0 = blockIdx.x * 64;
    const float scale = 0.125f;

    int lr  = tid >> 2;
    int lc0 = (tid & 3) * 4;

    {
        const float* qbase = qkv + ((size_t)(b * SEQ + q0 + lr)) * QKVN + h * HDIM;
        #pragma unroll
        for (int j = 0; j < 4; j++)
            *(float4*)&Qs[lr * AT_STRIDE + lc0 + j * 16] = *(const float4*)(qbase + lc0 + j * 16);
    }

    int ty = tid >> 4, tx = tid & 15;

    float m[4], l[4], acc[4][4];
    #pragma unroll
    for (int i = 0; i < 4; i++) {
        m[i] = -INFINITY; l[i] = 0.0f;
        #pragma unroll
        for (int j = 0; j < 4; j++) acc[i][j] = 0.0f;
    }

    for (int kt = 0; kt < SEQ / 64; kt++) {
        __syncthreads();
        {
            const float* kbase = qkv + ((size_t)(b * SEQ + kt * 64 + lr)) * QKVN + DMODEL + h * HDIM;
            const float* vbase = kbase + DMODEL;
            #pragma unroll
            for (int j = 0; j < 4; j++) {
                *(float4*)&Ks[lr * AT_STRIDE + lc0 + j * 16] = *(const float4*)(kbase + lc0 + j * 16);
                *(float4*)&Vs[lr * AT_STRIDE + lc0 + j * 16] = *(const float4*)(vbase + lc0 + j * 16);
            }
            if (tid < 64)
                mb[tid] = (mask[b * SEQ + kt * 64 + tid] != 0) ? 0.0f : -1e9f;
        }
        __syncthreads();

        float sv[4][4];
        #pragma unroll
        for (int i = 0; i < 4; i++)
            #pragma unroll
            for (int j = 0; j < 4; j++) sv[i][j] = 0.0f;

        #pragma unroll 4
        for (int kk = 0; kk < 16; kk++) {
            float4 a[4], bb[4];
            #pragma unroll
            for (int i = 0; i < 4; i++) a[i]  = *(float4*)&Qs[(ty * 4 + i) * AT_STRIDE + kk * 4];
            #pragma unroll
            for (int j = 0; j < 4; j++) bb[j] = *(float4*)&Ks[(tx * 4 + j) * AT_STRIDE + kk * 4];
            #pragma unroll
            for (int i = 0; i < 4; i++)
                #pragma unroll
                for (int j = 0; j < 4; j++)
                    sv[i][j] += a[i].x * bb[j].x + a[i].y * bb[j].y + a[i].z * bb[j].z + a[i].w * bb[j].w;
        }

        #pragma unroll
        for (int i = 0; i < 4; i++)
            #pragma unroll
            for (int j = 0; j < 4; j++)
                sv[i][j] = sv[i][j] * scale + mb[tx * 4 + j];

        #pragma unroll
        for (int i = 0; i < 4; i++) {
            float rmax = fmaxf(fmaxf(sv[i][0], sv[i][1]), fmaxf(sv[i][2], sv[i][3]));
            #pragma unroll
            for (int o = 8; o > 0; o >>= 1)
                rmax = fmaxf(rmax, __shfl_xor_sync(0xffffffffu, rmax, o));
            float mnew = fmaxf(m[i], rmax);
            float fac  = __expf(m[i] - mnew);
            float ps[4]; float rs = 0.0f;
            #pragma unroll
            for (int j = 0; j < 4; j++) { ps[j] = __expf(sv[i][j] - mnew); rs += ps[j]; }
            #pragma unroll
            for (int o = 8; o > 0; o >>= 1)
                rs += __shfl_xor_sync(0xffffffffu, rs, o);
            l[i] = l[i] * fac + rs;
            m[i] = mnew;
            #pragma unroll
            for (int j = 0; j < 4; j++) acc[i][j] *= fac;
            #pragma unroll
            for (int j = 0; j < 4; j++)
                Ps[(ty * 4 + i) * AT_STRIDE + tx * 4 + j] = ps[j];
        }
        __syncthreads();

        #pragma unroll 4
        for (int c = 0; c < 64; c++) {
            float4 vv = *(float4*)&Vs[c * AT_STRIDE + tx * 4];
            #pragma unroll
            for (int i = 0; i < 4; i++) {
                float pv = Ps[(ty * 4 + i) * AT_STRIDE + c];
                acc[i][0] += pv * vv.x;
                acc[i][1] += pv * vv.y;
                acc[i][2] += pv * vv.z;
                acc[i][3] += pv * vv.w;
            }
        }
    }

    #pragma unroll
    for (int i = 0; i < 4; i++) {
        float inv = 1.0f / l[i];
        float o0 = acc[i][0]*inv, o1 = acc[i][1]*inv, o2 = acc[i][2]*inv, o3 = acc[i][3]*inv;
        __nv_bfloat16 h0,h1,h2,h3,l0,l1,l2,l3;
        split_bf16(o0,h0,l0); split_bf16(o1,h1,l1); split_bf16(o2,h2,l2); split_bf16(o3,h3,l3);
        size_t off = ((size_t)(b * SEQ + q0 + ty * 4 + i)) * DMODEL + h * HDIM + tx * 4;
        *(uint2*)(oh + off) = make_uint2(pack2(h0,h1), pack2(h2,h3));
        *(uint2*)(ol + off) = make_uint2(pack2(l0,l1), pack2(l2,l3));
    }
}

// ---------------- host driver ----------------
extern "C" void kernel_launch(void* const* d_in, const int* in_sizes, int n_in,
                              void* d_out, int out_size)
{
    const float* x     = (const float*)d_in[0];
    const int*   mask  = (const int*)d_in[1];
    const float* Wq    = (const float*)d_in[2];
    const float* Wk    = (const float*)d_in[3];
    const float* Wv    = (const float*)d_in[4];
    const float* Wo    = (const float*)d_in[5];
    const float* ln1_g = (const float*)d_in[6];
    const float* ln1_b = (const float*)d_in[7];
    const float* ln2_g = (const float*)d_in[8];
    const float* ln2_b = (const float*)d_in[9];
    const float* W1    = (const float*)d_in[10];
    const float* b1    = (const float*)d_in[11];
    const float* W2    = (const float*)d_in[12];
    const float* b2    = (const float*)d_in[13];

    static float *px = nullptr, *pqkv;
    static __nv_bfloat16 *plnh, *plnl, *ppah, *ppal, *ppfh, *ppfl, *pwh, *pwl;
    if (!px) {
        cudaGetSymbolAddress((void**)&pqkv, g_qkv);
        cudaGetSymbolAddress((void**)&plnh, g_lnh);
        cudaGetSymbolAddress((void**)&plnl, g_lnl);
        cudaGetSymbolAddress((void**)&ppah, g_pah);
        cudaGetSymbolAddress((void**)&ppal, g_pal);
        cudaGetSymbolAddress((void**)&ppfh, g_pfh);
        cudaGetSymbolAddress((void**)&ppfl, g_pfl);
        cudaGetSymbolAddress((void**)&pwh, g_wth);
        cudaGetSymbolAddress((void**)&pwl, g_wtl);
        cudaFuncSetAttribute(attn_kernel, cudaFuncAttributeMaxDynamicSharedMemorySize, ATT_SMEM);
        cudaFuncSetAttribute(gemm_pipe<0,1,0>, cudaFuncAttributeMaxDynamicSharedMemorySize, GEMM_SMEM2);
        cudaFuncSetAttribute(gemm_pipe<1,1,0>, cudaFuncAttributeMaxDynamicSharedMemorySize, GEMM_SMEM2);
        cudaFuncSetAttribute(gemm_pipe<2,0,1>, cudaFuncAttributeMaxDynamicSharedMemorySize, GEMM_SMEM2);
        cudaFuncSetAttribute(gemm_pipe<3,1,0>, cudaFuncAttributeMaxDynamicSharedMemorySize, GEMM_SMEM2);
        cudaGetSymbolAddress((void**)&px, g_x);
    }

    // ---- weight convert+transpose ----
    {
        dim3 blk(32, 8);
        for (int l = 0; l < NLAYERS; l++) {
            size_t base = (size_t)l * WLAYER;
            dim3 gDD(DMODEL / 32, DMODEL / 32);
            wconv_kernel<<<gDD, blk>>>(Wq + (size_t)l * DMODEL * DMODEL, pwh + base,           pwl + base,           DMODEL, DMODEL);
            wconv_kernel<<<gDD, blk>>>(Wk + (size_t)l * DMODEL * DMODEL, pwh + base + 262144,  pwl + base + 262144,  DMODEL, DMODEL);
            wconv_kernel<<<gDD, blk>>>(Wv + (size_t)l * DMODEL * DMODEL, pwh + base + 524288,  pwl + base + 524288,  DMODEL, DMODEL);
            wconv_kernel<<<gDD, blk>>>(Wo + (size_t)l * DMODEL * DMODEL, pwh + base + 786432,  pwl + base + 786432,  DMODEL, DMODEL);
            dim3 g1(DFF / 32, DMODEL / 32);
            wconv_kernel<<<g1, blk>>>(W1 + (size_t)l * DMODEL * DFF,     pwh + base + 1048576, pwl + base + 1048576, DMODEL, DFF);
            dim3 g2(DMODEL / 32, DFF / 32);
            wconv_kernel<<<g2, blk>>>(W2 + (size_t)l * DFF * DMODEL,     pwh + base + 2097152, pwl + base + 2097152, DFF, DMODEL);
        }
    }

    posenc_kernel<<<(MROWS * DMODEL + 255) / 256, 256>>>(x, px);

    dim3 gQ(QKVN / 128,   MROWS / 128);     // 12 x 64
    dim3 gD(DMODEL / 128, MROWS / 128);     // 4 x 64
    dim3 gF(DFF / 128,    MROWS / 128);     // 16 x 64
    dim3 gA(SEQ / 64, BATCH * NHEAD);

    for (int l = 0; l < NLAYERS; l++) {
        size_t base = (size_t)l * WLAYER;
        const __nv_bfloat16 *qkvh = pwh + base,            *qkvl = pwl + base;
        const __nv_bfloat16 *ohp  = pwh + base + 786432,   *olp  = pwl + base + 786432;
        const __nv_bfloat16 *f1h  = pwh + base + 1048576,  *f1l  = pwl + base + 1048576;
        const __nv_bfloat16 *f2h  = pwh + base + 2097152,  *f2l  = pwl + base + 2097152;

        ln_kernel<<<MROWS, 128>>>(px, ln1_g + l * DMODEL, ln1_b + l * DMODEL, plnh, plnl);

        gemm_pipe<0,1,0><<<gQ, 256, GEMM_SMEM2>>>(plnh, plnl, qkvh, qkvl, nullptr, nullptr,
                                                  pqkv, nullptr, nullptr, DMODEL, QKVN);

        attn_kernel<<<gA, 256, ATT_SMEM>>>(pqkv, mask, ppah, ppal);

        gemm_pipe<1,1,0><<<gD, 256, GEMM_SMEM2>>>(ppah, ppal, ohp, olp, nullptr, px,
                                                  px, nullptr, nullptr, DMODEL, DMODEL);

        ln_kernel<<<MROWS, 128>>>(px, ln2_g + l * DMODEL, ln2_b + l * DMODEL, plnh, plnl);

        gemm_pipe<2,0,1><<<gF, 256, GEMM_SMEM2>>>(plnh, plnl, f1h, f1l, b1 + (size_t)l * DFF, nullptr,
                                                  nullptr, ppfh, ppfl, DMODEL, DFF);

        float* outp = (l == NLAYERS - 1) ? (float*)d_out : px;
        gemm_pipe<3,1,0><<<gD, 256, GEMM_SMEM2>>>(ppfh, ppfl, f2h, f2l, b2 + (size_t)l * DMODEL, px,
                                                  outp, nullptr, nullptr, DFF, DMODEL);
    }
}

// round 7
// speedup vs baseline: 2.8904x; 1.9893x over previous
#include <cuda_runtime.h>
#include <cuda_bf16.h>
#include <cuda_fp16.h>
#include <math.h>
#include <stdint.h>

// ---------------- problem constants ----------------
#define NLAYERS 4
#define DMODEL  512
#define NHEAD   8
#define HDIM    64
#define DFF     2048
#define BATCH   8
#define SEQ     1024
#define MROWS   (BATCH*SEQ)
#define LN_EPS  1e-3f
#define QKVN    1536

#define WLAYER  3145728
#define WT_ELEMS (NLAYERS*WLAYER)

// ---------------- device scratch ----------------
__device__ float g_x   [MROWS*DMODEL];
__device__ float g_qkv [MROWS*QKVN];
__device__ __nv_bfloat16 g_lnh[MROWS*DMODEL];
__device__ __nv_bfloat16 g_lnl[MROWS*DMODEL];
__device__ __nv_bfloat16 g_pah[MROWS*DMODEL];
__device__ __nv_bfloat16 g_pal[MROWS*DMODEL];
__device__ __nv_bfloat16 g_pfh[MROWS*DFF];
__device__ __nv_bfloat16 g_pfl[MROWS*DFF];
__device__ uint4 g_wth [WT_ELEMS/8];
__device__ uint4 g_wtl [WT_ELEMS/8];

extern __shared__ char dyn_smem[];

// ---------------- helpers ----------------
__device__ __forceinline__ uint32_t smem_u32(const void* p) {
    uint32_t a;
    asm("{ .reg .u64 t; cvta.to.shared.u64 t, %1; cvt.u32.u64 %0, t; }" : "=r"(a) : "l"(p));
    return a;
}
__device__ __forceinline__ void mma16816(float* c, const uint32_t* a, uint32_t b0, uint32_t b1) {
    asm volatile(
        "mma.sync.aligned.m16n8k16.row.col.f32.bf16.bf16.f32 "
        "{%0,%1,%2,%3}, {%4,%5,%6,%7}, {%8,%9}, {%0,%1,%2,%3};"
        : "+f"(c[0]), "+f"(c[1]), "+f"(c[2]), "+f"(c[3])
        : "r"(a[0]), "r"(a[1]), "r"(a[2]), "r"(a[3]), "r"(b0), "r"(b1));
}
__device__ __forceinline__ void mma16816h(float* c, const uint32_t* a, uint32_t b0, uint32_t b1) {
    asm volatile(
        "mma.sync.aligned.m16n8k16.row.col.f32.f16.f16.f32 "
        "{%0,%1,%2,%3}, {%4,%5,%6,%7}, {%8,%9}, {%0,%1,%2,%3};"
        : "+f"(c[0]), "+f"(c[1]), "+f"(c[2]), "+f"(c[3])
        : "r"(a[0]), "r"(a[1]), "r"(a[2]), "r"(a[3]), "r"(b0), "r"(b1));
}
__device__ __forceinline__ void cpasync16(uint32_t saddr, const void* gptr) {
    asm volatile("cp.async.cg.shared.global [%0], [%1], 16;" :: "r"(saddr), "l"(gptr));
}
__device__ __forceinline__ void cp_commit() { asm volatile("cp.async.commit_group;" ::: "memory"); }
__device__ __forceinline__ void cp_wait1()  { asm volatile("cp.async.wait_group 1;"  ::: "memory"); }
__device__ __forceinline__ void cp_wait0()  { asm volatile("cp.async.wait_group 0;"  ::: "memory"); }

__device__ __forceinline__ void split_bf16(float v, __nv_bfloat16& h, __nv_bfloat16& l) {
    h = __float2bfloat16(v);
    l = __float2bfloat16(v - __bfloat162float(h));
}
__device__ __forceinline__ uint32_t pack2(__nv_bfloat16 a, __nv_bfloat16 b) {
    return (uint32_t)__bfloat16_as_ushort(a) | ((uint32_t)__bfloat16_as_ushort(b) << 16);
}
__device__ __forceinline__ uint32_t ph2(float x, float y) {
    __half2 h = __floats2half2_rn(x, y);
    return *(uint32_t*)&h;
}

// ---------------- positional encoding ----------------
__global__ void posenc_kernel(const float* __restrict__ x, float* __restrict__ out) {
    int idx = blockIdx.x * 256 + threadIdx.x;
    if (idx >= MROWS * DMODEL) return;
    int d = idx & (DMODEL - 1);
    int s = (idx / DMODEL) & (SEQ - 1);
    const int half = DMODEL / 2;
    float val;
    if (d < half) {
        float ang = (float)s * expf(-logf(10000.0f) * (2.0f * (float)d / (float)DMODEL));
        val = sinf(ang);
    } else {
        float j = (float)(d - half);
        float ang = (float)s * expf(-logf(10000.0f) * (2.0f * j / (float)DMODEL));
        val = cosf(ang);
    }
    out[idx] = x[idx] + val;
}

// ---------------- layernorm -> bf16 hi/lo ----------------
__global__ void ln_kernel(const float* __restrict__ x, const float* __restrict__ gamma,
                          const float* __restrict__ beta,
                          __nv_bfloat16* __restrict__ oh, __nv_bfloat16* __restrict__ ol) {
    int row = blockIdx.x;
    int t = threadIdx.x;
    const float4* xr = (const float4*)(x + (size_t)row * DMODEL);
    float4 v = xr[t];

    __shared__ float red1[4];
    __shared__ float red2[4];

    float s = v.x + v.y + v.z + v.w;
    #pragma unroll
    for (int o = 16; o > 0; o >>= 1) s += __shfl_xor_sync(0xffffffffu, s, o);
    if ((t & 31) == 0) red1[t >> 5] = s;
    __syncthreads();
    float mean = (red1[0] + red1[1] + red1[2] + red1[3]) * (1.0f / DMODEL);

    float dx = v.x - mean, dy = v.y - mean, dz = v.z - mean, dw = v.w - mean;
    float s2 = dx*dx + dy*dy + dz*dz + dw*dw;
    #pragma unroll
    for (int o = 16; o > 0; o >>= 1) s2 += __shfl_xor_sync(0xffffffffu, s2, o);
    if ((t & 31) == 0) red2[t >> 5] = s2;
    __syncthreads();
    float var = (red2[0] + red2[1] + red2[2] + red2[3]) * (1.0f / DMODEL);
    float rs = rsqrtf(var + LN_EPS);

    float4 g4 = ((const float4*)gamma)[t];
    float4 b4 = ((const float4*)beta)[t];
    float o0 = dx * rs * g4.x + b4.x;
    float o1 = dy * rs * g4.y + b4.y;
    float o2 = dz * rs * g4.z + b4.z;
    float o3 = dw * rs * g4.w + b4.w;
    __nv_bfloat16 h0,h1,h2,h3,l0,l1,l2,l3;
    split_bf16(o0,h0,l0); split_bf16(o1,h1,l1); split_bf16(o2,h2,l2); split_bf16(o3,h3,l3);
    *(uint2*)(oh + (size_t)row * DMODEL + t * 4) = make_uint2(pack2(h0,h1), pack2(h2,h3));
    *(uint2*)(ol + (size_t)row * DMODEL + t * 4) = make_uint2(pack2(l0,l1), pack2(l2,l3));
}

// ---------------- weight convert+transpose ----------------
__global__ void wconv_kernel(const float* __restrict__ W,
                             __nv_bfloat16* __restrict__ Oh, __nv_bfloat16* __restrict__ Ol,
                             int K, int N) {
    __shared__ float tile[32][33];
    int tn = blockIdx.x * 32, tk = blockIdx.y * 32;
    int tx = threadIdx.x, ty = threadIdx.y;
    #pragma unroll
    for (int i = 0; i < 4; i++)
        tile[ty + i * 8][tx] = W[(size_t)(tk + ty + i * 8) * N + tn + tx];
    __syncthreads();
    #pragma unroll
    for (int i = 0; i < 4; i++) {
        int nl = ty + i * 8;
        float v = tile[tx][nl];
        __nv_bfloat16 h, l;
        split_bf16(v, h, l);
        size_t o = (size_t)(tn + nl) * K + tk + tx;
        Oh[o] = h;
        Ol[o] = l;
    }
}

// ---------------- pipelined bf16x3 mma GEMM ----------------
#define BKP 20
#define ARR_STRIDE (128 * BKP)
#define STAGE_BYTES (4 * ARR_STRIDE * 4)
#define GEMM_SMEM2 (2 * STAGE_BYTES)

template<int EPI, int OUTF32, int OUTBF16>
__global__ __launch_bounds__(256) void gemm_pipe(
    const __nv_bfloat16* __restrict__ Ah, const __nv_bfloat16* __restrict__ Al,
    const __nv_bfloat16* __restrict__ Wh, const __nv_bfloat16* __restrict__ Wl,
    const float* __restrict__ bias, const float* __restrict__ res,
    float* __restrict__ Cf, __nv_bfloat16* __restrict__ Ch, __nv_bfloat16* __restrict__ Cl,
    int K, int N)
{
    uint32_t sbase = smem_u32(dyn_smem);
    int tid = threadIdx.x;
    int lane = tid & 31, wid = tid >> 5;
    int wm = wid >> 1, wn = wid & 1;
    int m0 = blockIdx.y * 128, n0 = blockIdx.x * 128;
    int g = lane >> 2, t = lane & 3;

    int lrow = tid >> 1;
    int lhalf = tid & 1;

    const __nv_bfloat16* agh = Ah + (size_t)(m0 + lrow) * K;
    const __nv_bfloat16* agl = Al + (size_t)(m0 + lrow) * K;
    const __nv_bfloat16* bgh = Wh + (size_t)(n0 + lrow) * K;
    const __nv_bfloat16* bgl = Wl + (size_t)(n0 + lrow) * K;
    uint32_t srow = sbase + (uint32_t)(lrow * BKP) * 4;

    auto issue_load = [&](int kb, int st) {
        uint32_t so = srow + (uint32_t)st * STAGE_BYTES;
        #pragma unroll
        for (int p = 0; p < 2; p++) {
            int q = lhalf * 2 + p;
            int ge = kb + q * 8;
            uint32_t sb2 = so + (uint32_t)(q * 16);
            cpasync16(sb2,                          agh + ge);
            cpasync16(sb2 + ARR_STRIDE * 4,         agl + ge);
            cpasync16(sb2 + 2 * ARR_STRIDE * 4,     bgh + ge);
            cpasync16(sb2 + 3 * ARR_STRIDE * 4,     bgl + ge);
        }
        cp_commit();
    };

    float c[2][8][4];
    #pragma unroll
    for (int mt = 0; mt < 2; mt++)
        #pragma unroll
        for (int nt = 0; nt < 8; nt++)
            #pragma unroll
            for (int e = 0; e < 4; e++) c[mt][nt][e] = 0.0f;

    const int nkb = K >> 5;
    issue_load(0, 0);

    for (int kb = 0; kb < nkb; kb++) {
        int st = kb & 1;
        if (kb + 1 < nkb) issue_load((kb + 1) << 5, st ^ 1);
        if (kb + 1 < nkb) cp_wait1(); else cp_wait0();
        __syncthreads();

        uint32_t* As_h = (uint32_t*)(dyn_smem + st * STAGE_BYTES);
        uint32_t* As_l = As_h + ARR_STRIDE;
        uint32_t* Bs_h = As_h + 2 * ARR_STRIDE;
        uint32_t* Bs_l = As_h + 3 * ARR_STRIDE;

        #pragma unroll
        for (int s = 0; s < 2; s++) {
            uint32_t ahf[2][4], alf[2][4];
            #pragma unroll
            for (int mt = 0; mt < 2; mt++) {
                int base = (wm * 32 + mt * 16 + g) * BKP + s * 8 + t;
                ahf[mt][0] = As_h[base];
                ahf[mt][1] = As_h[base + 8 * BKP];
                ahf[mt][2] = As_h[base + 4];
                ahf[mt][3] = As_h[base + 8 * BKP + 4];
                alf[mt][0] = As_l[base];
                alf[mt][1] = As_l[base + 8 * BKP];
                alf[mt][2] = As_l[base + 4];
                alf[mt][3] = As_l[base + 8 * BKP + 4];
            }
            #pragma unroll
            for (int nt = 0; nt < 8; nt++) {
                int bbase = (wn * 64 + nt * 8 + g) * BKP + s * 8 + t;
                uint32_t bh0 = Bs_h[bbase], bh1 = Bs_h[bbase + 4];
                uint32_t bl0 = Bs_l[bbase], bl1 = Bs_l[bbase + 4];
                #pragma unroll
                for (int mt = 0; mt < 2; mt++) {
                    mma16816(c[mt][nt], ahf[mt], bh0, bh1);
                    mma16816(c[mt][nt], alf[mt], bh0, bh1);
                    mma16816(c[mt][nt], ahf[mt], bl0, bl1);
                }
            }
        }
        __syncthreads();
    }

    #pragma unroll
    for (int mt = 0; mt < 2; mt++) {
        #pragma unroll
        for (int nt = 0; nt < 8; nt++) {
            int row = m0 + wm * 32 + mt * 16 + g;
            int col = n0 + wn * 64 + nt * 8 + t * 2;
            float2 v1 = make_float2(c[mt][nt][0], c[mt][nt][1]);
            float2 v2 = make_float2(c[mt][nt][2], c[mt][nt][3]);
            if (EPI == 2 || EPI == 3) {
                float2 bb = *(const float2*)(bias + col);
                v1.x += bb.x; v1.y += bb.y;
                v2.x += bb.x; v2.y += bb.y;
            }
            if (EPI == 2) {
                v1.x = fmaxf(v1.x, 0.0f); v1.y = fmaxf(v1.y, 0.0f);
                v2.x = fmaxf(v2.x, 0.0f); v2.y = fmaxf(v2.y, 0.0f);
            }
            if (EPI == 1 || EPI == 3) {
                float2 r1 = *(const float2*)(res + (size_t)row * N + col);
                float2 r2 = *(const float2*)(res + (size_t)(row + 8) * N + col);
                v1.x += r1.x; v1.y += r1.y;
                v2.x += r2.x; v2.y += r2.y;
            }
            if (OUTF32) {
                *(float2*)(Cf + (size_t)row * N + col) = v1;
                *(float2*)(Cf + (size_t)(row + 8) * N + col) = v2;
            }
            if (OUTBF16) {
                __nv_bfloat16 h0,h1,l0,l1;
                split_bf16(v1.x, h0, l0); split_bf16(v1.y, h1, l1);
                *(uint32_t*)(Ch + (size_t)row * N + col) = pack2(h0, h1);
                *(uint32_t*)(Cl + (size_t)row * N + col) = pack2(l0, l1);
                split_bf16(v2.x, h0, l0); split_bf16(v2.y, h1, l1);
                *(uint32_t*)(Ch + (size_t)(row + 8) * N + col) = pack2(h0, h1);
                *(uint32_t*)(Cl + (size_t)(row + 8) * N + col) = pack2(l0, l1);
            }
        }
    }
}

// ---------------- tensor-core flash attention (fp16 mma) ----------------
// CTA: 128 q rows, 8 warps x 16 rows; K/V tiles of 64 keys.
#define AQP 36                                   // u32 row stride
#define ATT_SMEM (((128 + 64 + 64) * AQP) * 4 + 256)

__global__ __launch_bounds__(256) void attn_mma(
    const float* __restrict__ qkv, const int* __restrict__ mask,
    __nv_bfloat16* __restrict__ oh, __nv_bfloat16* __restrict__ ol)
{
    uint32_t* Qs = (uint32_t*)dyn_smem;          // 128*AQP
    uint32_t* Ks = Qs + 128 * AQP;                // 64*AQP
    uint32_t* Vt = Ks + 64 * AQP;                 // 64*AQP (transposed [hd][key])
    float* mb = (float*)(Vt + 64 * AQP);          // 64

    int tid = threadIdx.x;
    int lane = tid & 31, wid = tid >> 5;
    int g = lane >> 2, t = lane & 3;
    int b = blockIdx.y >> 3, h = blockIdx.y & 7;
    int q0 = blockIdx.x * 128;
    const float scale = 0.125f;

    // ---- load Q (fp32 -> fp16 smem), 128 rows x 64 cols ----
    #pragma unroll
    for (int p = 0; p < 8; p++) {
        int idx = tid + p * 256;
        int row = idx >> 4, c4 = (idx & 15) * 4;
        float4 f = *(const float4*)(qkv + (size_t)(b * SEQ + q0 + row) * QKVN + h * HDIM + c4);
        Qs[row * AQP + c4 / 2]     = ph2(f.x, f.y);
        Qs[row * AQP + c4 / 2 + 1] = ph2(f.z, f.w);
    }

    float m2[2] = {-INFINITY, -INFINITY};
    float l2[2] = {0.0f, 0.0f};
    float o[8][4];
    #pragma unroll
    for (int nt = 0; nt < 8; nt++)
        #pragma unroll
        for (int e = 0; e < 4; e++) o[nt][e] = 0.0f;

    int qrow = wid * 16;

    for (int kt = 0; kt < SEQ / 64; kt++) {
        __syncthreads();
        // K tile 64x64
        #pragma unroll
        for (int p = 0; p < 4; p++) {
            int idx = tid + p * 256;
            int row = idx >> 4, c4 = (idx & 15) * 4;
            float4 f = *(const float4*)(qkv + (size_t)(b * SEQ + kt * 64 + row) * QKVN + DMODEL + h * HDIM + c4);
            Ks[row * AQP + c4 / 2]     = ph2(f.x, f.y);
            Ks[row * AQP + c4 / 2 + 1] = ph2(f.z, f.w);
        }
        // V tile 64x64 -> transposed fp16 Vt[hd][key]
        #pragma unroll
        for (int it = 0; it < 2; it++) {
            int hd0 = ((tid >> 5) + it * 8) * 4;
            int kp = tid & 31;
            const float* v0 = qkv + (size_t)(b * SEQ + kt * 64 + kp * 2) * QKVN + 2 * DMODEL + h * HDIM + hd0;
            float4 fa = *(const float4*)v0;
            float4 fb = *(const float4*)(v0 + QKVN);
            Vt[(hd0 + 0) * AQP + kp] = ph2(fa.x, fb.x);
            Vt[(hd0 + 1) * AQP + kp] = ph2(fa.y, fb.y);
            Vt[(hd0 + 2) * AQP + kp] = ph2(fa.z, fb.z);
            Vt[(hd0 + 3) * AQP + kp] = ph2(fa.w, fb.w);
        }
        if (tid < 64)
            mb[tid] = (mask[b * SEQ + kt * 64 + tid] != 0) ? 0.0f : -1e9f;
        __syncthreads();

        // ---- S = Q K^T ----
        float sv[8][4];
        #pragma unroll
        for (int nt = 0; nt < 8; nt++)
            #pragma unroll
            for (int e = 0; e < 4; e++) sv[nt][e] = 0.0f;

        #pragma unroll
        for (int s = 0; s < 4; s++) {
            uint32_t a[4];
            int ab = (qrow + g) * AQP + s * 8 + t;
            a[0] = Qs[ab];
            a[1] = Qs[ab + 8 * AQP];
            a[2] = Qs[ab + 4];
            a[3] = Qs[ab + 8 * AQP + 4];
            #pragma unroll
            for (int nt = 0; nt < 8; nt++) {
                int bb = (nt * 8 + g) * AQP + s * 8 + t;
                mma16816h(sv[nt], a, Ks[bb], Ks[bb + 4]);
            }
        }

        // ---- mask + scale, row max ----
        float rm0 = -INFINITY, rm1 = -INFINITY;
        #pragma unroll
        for (int nt = 0; nt < 8; nt++) {
            int col = nt * 8 + t * 2;
            float mb0 = mb[col], mb1 = mb[col + 1];
            sv[nt][0] = sv[nt][0] * scale + mb0;
            sv[nt][1] = sv[nt][1] * scale + mb1;
            sv[nt][2] = sv[nt][2] * scale + mb0;
            sv[nt][3] = sv[nt][3] * scale + mb1;
            rm0 = fmaxf(rm0, fmaxf(sv[nt][0], sv[nt][1]));
            rm1 = fmaxf(rm1, fmaxf(sv[nt][2], sv[nt][3]));
        }
        #pragma unroll
        for (int ox = 1; ox <= 2; ox <<= 1) {
            rm0 = fmaxf(rm0, __shfl_xor_sync(0xffffffffu, rm0, ox));
            rm1 = fmaxf(rm1, __shfl_xor_sync(0xffffffffu, rm1, ox));
        }
        float mn0 = fmaxf(m2[0], rm0), mn1 = fmaxf(m2[1], rm1);
        float f0 = __expf(m2[0] - mn0), f1 = __expf(m2[1] - mn1);
        m2[0] = mn0; m2[1] = mn1;

        float rs0 = 0.0f, rs1 = 0.0f;
        #pragma unroll
        for (int nt = 0; nt < 8; nt++) {
            sv[nt][0] = __expf(sv[nt][0] - mn0);
            sv[nt][1] = __expf(sv[nt][1] - mn0);
            sv[nt][2] = __expf(sv[nt][2] - mn1);
            sv[nt][3] = __expf(sv[nt][3] - mn1);
            rs0 += sv[nt][0] + sv[nt][1];
            rs1 += sv[nt][2] + sv[nt][3];
        }
        #pragma unroll
        for (int ox = 1; ox <= 2; ox <<= 1) {
            rs0 += __shfl_xor_sync(0xffffffffu, rs0, ox);
            rs1 += __shfl_xor_sync(0xffffffffu, rs1, ox);
        }
        l2[0] = l2[0] * f0 + rs0;
        l2[1] = l2[1] * f1 + rs1;
        #pragma unroll
        for (int nt = 0; nt < 8; nt++) {
            o[nt][0] *= f0; o[nt][1] *= f0;
            o[nt][2] *= f1; o[nt][3] *= f1;
        }

        // ---- O += P V  (P A-frags straight from S accumulators) ----
        #pragma unroll
        for (int s = 0; s < 4; s++) {
            uint32_t a[4];
            a[0] = ph2(sv[2 * s][0],     sv[2 * s][1]);
            a[1] = ph2(sv[2 * s][2],     sv[2 * s][3]);
            a[2] = ph2(sv[2 * s + 1][0], sv[2 * s + 1][1]);
            a[3] = ph2(sv[2 * s + 1][2], sv[2 * s + 1][3]);
            #pragma unroll
            for (int nt = 0; nt < 8; nt++) {
                int bb = (nt * 8 + g) * AQP + s * 8 + t;
                mma16816h(o[nt], a, Vt[bb], Vt[bb + 4]);
            }
        }
    }

    // ---- epilogue: O/l -> bf16 hi/lo split ----
    float i0 = 1.0f / l2[0], i1 = 1.0f / l2[1];
    #pragma unroll
    for (int nt = 0; nt < 8; nt++) {
        size_t row0 = (size_t)(b * SEQ + q0 + qrow + g) * DMODEL + h * HDIM + nt * 8 + t * 2;
        size_t row1 = row0 + 8 * DMODEL;
        __nv_bfloat16 hh0, hh1, ll0, ll1;
        split_bf16(o[nt][0] * i0, hh0, ll0);
        split_bf16(o[nt][1] * i0, hh1, ll1);
        *(uint32_t*)(oh + row0) = pack2(hh0, hh1);
        *(uint32_t*)(ol + row0) = pack2(ll0, ll1);
        split_bf16(o[nt][2] * i1, hh0, ll0);
        split_bf16(o[nt][3] * i1, hh1, ll1);
        *(uint32_t*)(oh + row1) = pack2(hh0, hh1);
        *(uint32_t*)(ol + row1) = pack2(ll0, ll1);
    }
}

// ---------------- host driver ----------------
extern "C" void kernel_launch(void* const* d_in, const int* in_sizes, int n_in,
                              void* d_out, int out_size)
{
    const float* x     = (const float*)d_in[0];
    const int*   mask  = (const int*)d_in[1];
    const float* Wq    = (const float*)d_in[2];
    const float* Wk    = (const float*)d_in[3];
    const float* Wv    = (const float*)d_in[4];
    const float* Wo    = (const float*)d_in[5];
    const float* ln1_g = (const float*)d_in[6];
    const float* ln1_b = (const float*)d_in[7];
    const float* ln2_g = (const float*)d_in[8];
    const float* ln2_b = (const float*)d_in[9];
    const float* W1    = (const float*)d_in[10];
    const float* b1    = (const float*)d_in[11];
    const float* W2    = (const float*)d_in[12];
    const float* b2    = (const float*)d_in[13];

    static float *px = nullptr, *pqkv;
    static __nv_bfloat16 *plnh, *plnl, *ppah, *ppal, *ppfh, *ppfl, *pwh, *pwl;
    if (!px) {
        cudaGetSymbolAddress((void**)&pqkv, g_qkv);
        cudaGetSymbolAddress((void**)&plnh, g_lnh);
        cudaGetSymbolAddress((void**)&plnl, g_lnl);
        cudaGetSymbolAddress((void**)&ppah, g_pah);
        cudaGetSymbolAddress((void**)&ppal, g_pal);
        cudaGetSymbolAddress((void**)&ppfh, g_pfh);
        cudaGetSymbolAddress((void**)&ppfl, g_pfl);
        cudaGetSymbolAddress((void**)&pwh, g_wth);
        cudaGetSymbolAddress((void**)&pwl, g_wtl);
        cudaFuncSetAttribute(gemm_pipe<0,1,0>, cudaFuncAttributeMaxDynamicSharedMemorySize, GEMM_SMEM2);
        cudaFuncSetAttribute(gemm_pipe<1,1,0>, cudaFuncAttributeMaxDynamicSharedMemorySize, GEMM_SMEM2);
        cudaFuncSetAttribute(gemm_pipe<2,0,1>, cudaFuncAttributeMaxDynamicSharedMemorySize, GEMM_SMEM2);
        cudaFuncSetAttribute(gemm_pipe<3,1,0>, cudaFuncAttributeMaxDynamicSharedMemorySize, GEMM_SMEM2);
        cudaGetSymbolAddress((void**)&px, g_x);
    }

    // ---- weight convert+transpose ----
    {
        dim3 blk(32, 8);
        for (int l = 0; l < NLAYERS; l++) {
            size_t base = (size_t)l * WLAYER;
            dim3 gDD(DMODEL / 32, DMODEL / 32);
            wconv_kernel<<<gDD, blk>>>(Wq + (size_t)l * DMODEL * DMODEL, pwh + base,           pwl + base,           DMODEL, DMODEL);
            wconv_kernel<<<gDD, blk>>>(Wk + (size_t)l * DMODEL * DMODEL, pwh + base + 262144,  pwl + base + 262144,  DMODEL, DMODEL);
            wconv_kernel<<<gDD, blk>>>(Wv + (size_t)l * DMODEL * DMODEL, pwh + base + 524288,  pwl + base + 524288,  DMODEL, DMODEL);
            wconv_kernel<<<gDD, blk>>>(Wo + (size_t)l * DMODEL * DMODEL, pwh + base + 786432,  pwl + base + 786432,  DMODEL, DMODEL);
            dim3 g1(DFF / 32, DMODEL / 32);
            wconv_kernel<<<g1, blk>>>(W1 + (size_t)l * DMODEL * DFF,     pwh + base + 1048576, pwl + base + 1048576, DMODEL, DFF);
            dim3 g2(DMODEL / 32, DFF / 32);
            wconv_kernel<<<g2, blk>>>(W2 + (size_t)l * DFF * DMODEL,     pwh + base + 2097152, pwl + base + 2097152, DFF, DMODEL);
        }
    }

    posenc_kernel<<<(MROWS * DMODEL + 255) / 256, 256>>>(x, px);

    dim3 gQ(QKVN / 128,   MROWS / 128);
    dim3 gD(DMODEL / 128, MROWS / 128);
    dim3 gF(DFF / 128,    MROWS / 128);
    dim3 gA(SEQ / 128, BATCH * NHEAD);      // 8 x 64

    for (int l = 0; l < NLAYERS; l++) {
        size_t base = (size_t)l * WLAYER;
        const __nv_bfloat16 *qkvh = pwh + base,            *qkvl = pwl + base;
        const __nv_bfloat16 *ohp  = pwh + base + 786432,   *olp  = pwl + base + 786432;
        const __nv_bfloat16 *f1h  = pwh + base + 1048576,  *f1l  = pwl + base + 1048576;
        const __nv_bfloat16 *f2h  = pwh + base + 2097152,  *f2l  = pwl + base + 2097152;

        ln_kernel<<<MROWS, 128>>>(px, ln1_g + l * DMODEL, ln1_b + l * DMODEL, plnh, plnl);

        gemm_pipe<0,1,0><<<gQ, 256, GEMM_SMEM2>>>(plnh, plnl, qkvh, qkvl, nullptr, nullptr,
                                                  pqkv, nullptr, nullptr, DMODEL, QKVN);

        attn_mma<<<gA, 256, ATT_SMEM>>>(pqkv, mask, ppah, ppal);

        gemm_pipe<1,1,0><<<gD, 256, GEMM_SMEM2>>>(ppah, ppal, ohp, olp, nullptr, px,
                                                  px, nullptr, nullptr, DMODEL, DMODEL);

        ln_kernel<<<MROWS, 128>>>(px, ln2_g + l * DMODEL, ln2_b + l * DMODEL, plnh, plnl);

        gemm_pipe<2,0,1><<<gF, 256, GEMM_SMEM2>>>(plnh, plnl, f1h, f1l, b1 + (size_t)l * DFF, nullptr,
                                                  nullptr, ppfh, ppfl, DMODEL, DFF);

        float* outp = (l == NLAYERS - 1) ? (float*)d_out : px;
        gemm_pipe<3,1,0><<<gD, 256, GEMM_SMEM2>>>(ppfh, ppfl, f2h, f2l, b2 + (size_t)l * DMODEL, px,
                                                  outp, nullptr, nullptr, DFF, DMODEL);
    }
}

// round 8
// speedup vs baseline: 3.4636x; 1.1983x over previous
#include <cuda_runtime.h>
#include <cuda_bf16.h>
#include <cuda_fp16.h>
#include <math.h>
#include <stdint.h>

// ---------------- problem constants ----------------
#define NLAYERS 4
#define DMODEL  512
#define NHEAD   8
#define HDIM    64
#define DFF     2048
#define BATCH   8
#define SEQ     1024
#define MROWS   (BATCH*SEQ)
#define LN_EPS  1e-3f
#define QKVN    1536

#define WLAYER  3145728
#define WT_ELEMS (NLAYERS*WLAYER)

// ---------------- device scratch ----------------
__device__ float g_x   [MROWS*DMODEL];
__device__ float g_qkv [MROWS*QKVN];
__device__ __half g_lnh[MROWS*DMODEL];
__device__ __half g_lnl[MROWS*DMODEL];
__device__ __half g_pah[MROWS*DMODEL];
__device__ __half g_pal[MROWS*DMODEL];
__device__ __half g_pfh[MROWS*DFF];
__device__ __half g_pfl[MROWS*DFF];
__device__ uint4 g_wth [WT_ELEMS/8];     // weights fp16, [N][K] transposed

extern __shared__ char dyn_smem[];

// ---------------- helpers ----------------
__device__ __forceinline__ void mma16816h(float* c, const uint32_t* a, uint32_t b0, uint32_t b1) {
    asm volatile(
        "mma.sync.aligned.m16n8k16.row.col.f32.f16.f16.f32 "
        "{%0,%1,%2,%3}, {%4,%5,%6,%7}, {%8,%9}, {%0,%1,%2,%3};"
        : "+f"(c[0]), "+f"(c[1]), "+f"(c[2]), "+f"(c[3])
        : "r"(a[0]), "r"(a[1]), "r"(a[2]), "r"(a[3]), "r"(b0), "r"(b1));
}
__device__ __forceinline__ void cpasync16(uint32_t saddr, const void* gptr) {
    asm volatile("cp.async.cg.shared.global [%0], [%1], 16;" :: "r"(saddr), "l"(gptr));
}
__device__ __forceinline__ uint32_t smem_u32(const void* p) {
    uint32_t a;
    asm("{ .reg .u64 t; cvta.to.shared.u64 t, %1; cvt.u32.u64 %0, t; }" : "=r"(a) : "l"(p));
    return a;
}
__device__ __forceinline__ void cp_commit() { asm volatile("cp.async.commit_group;" ::: "memory"); }
__device__ __forceinline__ void cp_wait1()  { asm volatile("cp.async.wait_group 1;"  ::: "memory"); }
__device__ __forceinline__ void cp_wait0()  { asm volatile("cp.async.wait_group 0;"  ::: "memory"); }

__device__ __forceinline__ void split_f16(float v, __half& h, __half& l) {
    h = __float2half_rn(v);
    l = __float2half_rn(v - __half2float(h));
}
__device__ __forceinline__ uint32_t packh2(__half a, __half b) {
    return (uint32_t)__half_as_ushort(a) | ((uint32_t)__half_as_ushort(b) << 16);
}
__device__ __forceinline__ uint32_t ph2(float x, float y) {
    __half2 h = __floats2half2_rn(x, y);
    return *(uint32_t*)&h;
}

// ---------------- positional encoding ----------------
__global__ void posenc_kernel(const float* __restrict__ x, float* __restrict__ out) {
    int idx = blockIdx.x * 256 + threadIdx.x;
    if (idx >= MROWS * DMODEL) return;
    int d = idx & (DMODEL - 1);
    int s = (idx / DMODEL) & (SEQ - 1);
    const int half = DMODEL / 2;
    float val;
    if (d < half) {
        float ang = (float)s * expf(-logf(10000.0f) * (2.0f * (float)d / (float)DMODEL));
        val = sinf(ang);
    } else {
        float j = (float)(d - half);
        float ang = (float)s * expf(-logf(10000.0f) * (2.0f * j / (float)DMODEL));
        val = cosf(ang);
    }
    out[idx] = x[idx] + val;
}

// ---------------- layernorm -> fp16 hi/lo ----------------
__global__ void ln_kernel(const float* __restrict__ x, const float* __restrict__ gamma,
                          const float* __restrict__ beta,
                          __half* __restrict__ oh, __half* __restrict__ ol) {
    int row = blockIdx.x;
    int t = threadIdx.x;
    const float4* xr = (const float4*)(x + (size_t)row * DMODEL);
    float4 v = xr[t];

    __shared__ float red1[4];
    __shared__ float red2[4];

    float s = v.x + v.y + v.z + v.w;
    #pragma unroll
    for (int o = 16; o > 0; o >>= 1) s += __shfl_xor_sync(0xffffffffu, s, o);
    if ((t & 31) == 0) red1[t >> 5] = s;
    __syncthreads();
    float mean = (red1[0] + red1[1] + red1[2] + red1[3]) * (1.0f / DMODEL);

    float dx = v.x - mean, dy = v.y - mean, dz = v.z - mean, dw = v.w - mean;
    float s2 = dx*dx + dy*dy + dz*dz + dw*dw;
    #pragma unroll
    for (int o = 16; o > 0; o >>= 1) s2 += __shfl_xor_sync(0xffffffffu, s2, o);
    if ((t & 31) == 0) red2[t >> 5] = s2;
    __syncthreads();
    float var = (red2[0] + red2[1] + red2[2] + red2[3]) * (1.0f / DMODEL);
    float rs = rsqrtf(var + LN_EPS);

    float4 g4 = ((const float4*)gamma)[t];
    float4 b4 = ((const float4*)beta)[t];
    float o0 = dx * rs * g4.x + b4.x;
    float o1 = dy * rs * g4.y + b4.y;
    float o2 = dz * rs * g4.z + b4.z;
    float o3 = dw * rs * g4.w + b4.w;
    __half h0,h1,h2,h3,l0,l1,l2,l3;
    split_f16(o0,h0,l0); split_f16(o1,h1,l1); split_f16(o2,h2,l2); split_f16(o3,h3,l3);
    *(uint2*)(oh + (size_t)row * DMODEL + t * 4) = make_uint2(packh2(h0,h1), packh2(h2,h3));
    *(uint2*)(ol + (size_t)row * DMODEL + t * 4) = make_uint2(packh2(l0,l1), packh2(l2,l3));
}

// ---------------- weight convert+transpose: fp32 [K][N] -> fp16 [N][K] ----------------
__global__ void wconv_kernel(const float* __restrict__ W, __half* __restrict__ Oh,
                             int K, int N) {
    __shared__ float tile[32][33];
    int tn = blockIdx.x * 32, tk = blockIdx.y * 32;
    int tx = threadIdx.x, ty = threadIdx.y;
    #pragma unroll
    for (int i = 0; i < 4; i++)
        tile[ty + i * 8][tx] = W[(size_t)(tk + ty + i * 8) * N + tn + tx];
    __syncthreads();
    #pragma unroll
    for (int i = 0; i < 4; i++) {
        int nl = ty + i * 8;
        Oh[(size_t)(tn + nl) * K + tk + tx] = __float2half_rn(tile[tx][nl]);
    }
}

// ---------------- pipelined fp16x2 mma GEMM ----------------
// C = A[M,K] @ W[K,N];  A = Ah+Al fp16 pair (near-exact), W single fp16 [N][K].
// EPI: 0 plain, 1 +res, 2 relu(+bias), 3 +bias+res;  OUTF32 / OUTF16 outputs.
#define BKP 20
#define ARR_STRIDE (128 * BKP)
#define STAGE_BYTES (3 * ARR_STRIDE * 4)
#define GEMM_SMEM2 (2 * STAGE_BYTES)          // 61440

template<int EPI, int OUTF32, int OUTF16>
__global__ __launch_bounds__(256) void gemm_pipe(
    const __half* __restrict__ Ah, const __half* __restrict__ Al,
    const __half* __restrict__ Wh,
    const float* __restrict__ bias, const float* __restrict__ res,
    float* __restrict__ Cf, __half* __restrict__ Ch, __half* __restrict__ Cl,
    int K, int N)
{
    uint32_t sbase = smem_u32(dyn_smem);
    int tid = threadIdx.x;
    int lane = tid & 31, wid = tid >> 5;
    int wm = wid >> 1, wn = wid & 1;
    int m0 = blockIdx.y * 128, n0 = blockIdx.x * 128;
    int g = lane >> 2, t = lane & 3;

    int lrow = tid >> 1;
    int lhalf = tid & 1;

    const __half* agh = Ah + (size_t)(m0 + lrow) * K;
    const __half* agl = Al + (size_t)(m0 + lrow) * K;
    const __half* bgh = Wh + (size_t)(n0 + lrow) * K;
    uint32_t srow = sbase + (uint32_t)(lrow * BKP) * 4;

    auto issue_load = [&](int kb, int st) {
        uint32_t so = srow + (uint32_t)st * STAGE_BYTES;
        #pragma unroll
        for (int p = 0; p < 2; p++) {
            int q = lhalf * 2 + p;
            int ge = kb + q * 8;
            uint32_t sb2 = so + (uint32_t)(q * 16);
            cpasync16(sb2,                      agh + ge);
            cpasync16(sb2 + ARR_STRIDE * 4,     agl + ge);
            cpasync16(sb2 + 2 * ARR_STRIDE * 4, bgh + ge);
        }
        cp_commit();
    };

    float c[2][8][4];
    #pragma unroll
    for (int mt = 0; mt < 2; mt++)
        #pragma unroll
        for (int nt = 0; nt < 8; nt++)
            #pragma unroll
            for (int e = 0; e < 4; e++) c[mt][nt][e] = 0.0f;

    const int nkb = K >> 5;
    issue_load(0, 0);

    for (int kb = 0; kb < nkb; kb++) {
        int st = kb & 1;
        if (kb + 1 < nkb) issue_load((kb + 1) << 5, st ^ 1);
        if (kb + 1 < nkb) cp_wait1(); else cp_wait0();
        __syncthreads();

        uint32_t* As_h = (uint32_t*)(dyn_smem + st * STAGE_BYTES);
        uint32_t* As_l = As_h + ARR_STRIDE;
        uint32_t* Bs_h = As_h + 2 * ARR_STRIDE;

        #pragma unroll
        for (int s = 0; s < 2; s++) {
            uint32_t ahf[2][4], alf[2][4];
            #pragma unroll
            for (int mt = 0; mt < 2; mt++) {
                int base = (wm * 32 + mt * 16 + g) * BKP + s * 8 + t;
                ahf[mt][0] = As_h[base];
                ahf[mt][1] = As_h[base + 8 * BKP];
                ahf[mt][2] = As_h[base + 4];
                ahf[mt][3] = As_h[base + 8 * BKP + 4];
                alf[mt][0] = As_l[base];
                alf[mt][1] = As_l[base + 8 * BKP];
                alf[mt][2] = As_l[base + 4];
                alf[mt][3] = As_l[base + 8 * BKP + 4];
            }
            #pragma unroll
            for (int nt = 0; nt < 8; nt++) {
                int bbase = (wn * 64 + nt * 8 + g) * BKP + s * 8 + t;
                uint32_t bh0 = Bs_h[bbase], bh1 = Bs_h[bbase + 4];
                #pragma unroll
                for (int mt = 0; mt < 2; mt++) {
                    mma16816h(c[mt][nt], ahf[mt], bh0, bh1);
                    mma16816h(c[mt][nt], alf[mt], bh0, bh1);
                }
            }
        }
        __syncthreads();
    }

    #pragma unroll
    for (int mt = 0; mt < 2; mt++) {
        #pragma unroll
        for (int nt = 0; nt < 8; nt++) {
            int row = m0 + wm * 32 + mt * 16 + g;
            int col = n0 + wn * 64 + nt * 8 + t * 2;
            float2 v1 = make_float2(c[mt][nt][0], c[mt][nt][1]);
            float2 v2 = make_float2(c[mt][nt][2], c[mt][nt][3]);
            if (EPI == 2 || EPI == 3) {
                float2 bb = *(const float2*)(bias + col);
                v1.x += bb.x; v1.y += bb.y;
                v2.x += bb.x; v2.y += bb.y;
            }
            if (EPI == 2) {
                v1.x = fmaxf(v1.x, 0.0f); v1.y = fmaxf(v1.y, 0.0f);
                v2.x = fmaxf(v2.x, 0.0f); v2.y = fmaxf(v2.y, 0.0f);
            }
            if (EPI == 1 || EPI == 3) {
                float2 r1 = *(const float2*)(res + (size_t)row * N + col);
                float2 r2 = *(const float2*)(res + (size_t)(row + 8) * N + col);
                v1.x += r1.x; v1.y += r1.y;
                v2.x += r2.x; v2.y += r2.y;
            }
            if (OUTF32) {
                *(float2*)(Cf + (size_t)row * N + col) = v1;
                *(float2*)(Cf + (size_t)(row + 8) * N + col) = v2;
            }
            if (OUTF16) {
                __half h0,h1,l0,l1;
                split_f16(v1.x, h0, l0); split_f16(v1.y, h1, l1);
                *(uint32_t*)(Ch + (size_t)row * N + col) = packh2(h0, h1);
                *(uint32_t*)(Cl + (size_t)row * N + col) = packh2(l0, l1);
                split_f16(v2.x, h0, l0); split_f16(v2.y, h1, l1);
                *(uint32_t*)(Ch + (size_t)(row + 8) * N + col) = packh2(h0, h1);
                *(uint32_t*)(Cl + (size_t)(row + 8) * N + col) = packh2(l0, l1);
            }
        }
    }
}

// ---------------- tensor-core flash attention (fp16 mma) ----------------
#define AQP 36
#define ATT_SMEM (((128 + 64 + 64) * AQP) * 4 + 256)

__global__ __launch_bounds__(256) void attn_mma(
    const float* __restrict__ qkv, const int* __restrict__ mask,
    __half* __restrict__ oh, __half* __restrict__ ol)
{
    uint32_t* Qs = (uint32_t*)dyn_smem;
    uint32_t* Ks = Qs + 128 * AQP;
    uint32_t* Vt = Ks + 64 * AQP;
    float* mb = (float*)(Vt + 64 * AQP);

    int tid = threadIdx.x;
    int lane = tid & 31, wid = tid >> 5;
    int g = lane >> 2, t = lane & 3;
    int b = blockIdx.y >> 3, h = blockIdx.y & 7;
    int q0 = blockIdx.x * 128;
    const float scale = 0.125f;

    #pragma unroll
    for (int p = 0; p < 8; p++) {
        int idx = tid + p * 256;
        int row = idx >> 4, c4 = (idx & 15) * 4;
        float4 f = *(const float4*)(qkv + (size_t)(b * SEQ + q0 + row) * QKVN + h * HDIM + c4);
        Qs[row * AQP + c4 / 2]     = ph2(f.x, f.y);
        Qs[row * AQP + c4 / 2 + 1] = ph2(f.z, f.w);
    }

    float m2[2] = {-INFINITY, -INFINITY};
    float l2[2] = {0.0f, 0.0f};
    float o[8][4];
    #pragma unroll
    for (int nt = 0; nt < 8; nt++)
        #pragma unroll
        for (int e = 0; e < 4; e++) o[nt][e] = 0.0f;

    int qrow = wid * 16;

    for (int kt = 0; kt < SEQ / 64; kt++) {
        __syncthreads();
        #pragma unroll
        for (int p = 0; p < 4; p++) {
            int idx = tid + p * 256;
            int row = idx >> 4, c4 = (idx & 15) * 4;
            float4 f = *(const float4*)(qkv + (size_t)(b * SEQ + kt * 64 + row) * QKVN + DMODEL + h * HDIM + c4);
            Ks[row * AQP + c4 / 2]     = ph2(f.x, f.y);
            Ks[row * AQP + c4 / 2 + 1] = ph2(f.z, f.w);
        }
        #pragma unroll
        for (int it = 0; it < 2; it++) {
            int hd0 = ((tid >> 5) + it * 8) * 4;
            int kp = tid & 31;
            const float* v0 = qkv + (size_t)(b * SEQ + kt * 64 + kp * 2) * QKVN + 2 * DMODEL + h * HDIM + hd0;
            float4 fa = *(const float4*)v0;
            float4 fb = *(const float4*)(v0 + QKVN);
            Vt[(hd0 + 0) * AQP + kp] = ph2(fa.x, fb.x);
            Vt[(hd0 + 1) * AQP + kp] = ph2(fa.y, fb.y);
            Vt[(hd0 + 2) * AQP + kp] = ph2(fa.z, fb.z);
            Vt[(hd0 + 3) * AQP + kp] = ph2(fa.w, fb.w);
        }
        if (tid < 64)
            mb[tid] = (mask[b * SEQ + kt * 64 + tid] != 0) ? 0.0f : -1e9f;
        __syncthreads();

        float sv[8][4];
        #pragma unroll
        for (int nt = 0; nt < 8; nt++)
            #pragma unroll
            for (int e = 0; e < 4; e++) sv[nt][e] = 0.0f;

        #pragma unroll
        for (int s = 0; s < 4; s++) {
            uint32_t a[4];
            int ab = (qrow + g) * AQP + s * 8 + t;
            a[0] = Qs[ab];
            a[1] = Qs[ab + 8 * AQP];
            a[2] = Qs[ab + 4];
            a[3] = Qs[ab + 8 * AQP + 4];
            #pragma unroll
            for (int nt = 0; nt < 8; nt++) {
                int bb = (nt * 8 + g) * AQP + s * 8 + t;
                mma16816h(sv[nt], a, Ks[bb], Ks[bb + 4]);
            }
        }

        float rm0 = -INFINITY, rm1 = -INFINITY;
        #pragma unroll
        for (int nt = 0; nt < 8; nt++) {
            int col = nt * 8 + t * 2;
            float mb0 = mb[col], mb1 = mb[col + 1];
            sv[nt][0] = sv[nt][0] * scale + mb0;
            sv[nt][1] = sv[nt][1] * scale + mb1;
            sv[nt][2] = sv[nt][2] * scale + mb0;
            sv[nt][3] = sv[nt][3] * scale + mb1;
            rm0 = fmaxf(rm0, fmaxf(sv[nt][0], sv[nt][1]));
            rm1 = fmaxf(rm1, fmaxf(sv[nt][2], sv[nt][3]));
        }
        #pragma unroll
        for (int ox = 1; ox <= 2; ox <<= 1) {
            rm0 = fmaxf(rm0, __shfl_xor_sync(0xffffffffu, rm0, ox));
            rm1 = fmaxf(rm1, __shfl_xor_sync(0xffffffffu, rm1, ox));
        }
        float mn0 = fmaxf(m2[0], rm0), mn1 = fmaxf(m2[1], rm1);
        float f0 = __expf(m2[0] - mn0), f1 = __expf(m2[1] - mn1);
        m2[0] = mn0; m2[1] = mn1;

        float rs0 = 0.0f, rs1 = 0.0f;
        #pragma unroll
        for (int nt = 0; nt < 8; nt++) {
            sv[nt][0] = __expf(sv[nt][0] - mn0);
            sv[nt][1] = __expf(sv[nt][1] - mn0);
            sv[nt][2] = __expf(sv[nt][2] - mn1);
            sv[nt][3] = __expf(sv[nt][3] - mn1);
            rs0 += sv[nt][0] + sv[nt][1];
            rs1 += sv[nt][2] + sv[nt][3];
        }
        #pragma unroll
        for (int ox = 1; ox <= 2; ox <<= 1) {
            rs0 += __shfl_xor_sync(0xffffffffu, rs0, ox);
            rs1 += __shfl_xor_sync(0xffffffffu, rs1, ox);
        }
        l2[0] = l2[0] * f0 + rs0;
        l2[1] = l2[1] * f1 + rs1;
        #pragma unroll
        for (int nt = 0; nt < 8; nt++) {
            o[nt][0] *= f0; o[nt][1] *= f0;
            o[nt][2] *= f1; o[nt][3] *= f1;
        }

        #pragma unroll
        for (int s = 0; s < 4; s++) {
            uint32_t a[4];
            a[0] = ph2(sv[2 * s][0],     sv[2 * s][1]);
            a[1] = ph2(sv[2 * s][2],     sv[2 * s][3]);
            a[2] = ph2(sv[2 * s + 1][0], sv[2 * s + 1][1]);
            a[3] = ph2(sv[2 * s + 1][2], sv[2 * s + 1][3]);
            #pragma unroll
            for (int nt = 0; nt < 8; nt++) {
                int bb = (nt * 8 + g) * AQP + s * 8 + t;
                mma16816h(o[nt], a, Vt[bb], Vt[bb + 4]);
            }
        }
    }

    float i0 = 1.0f / l2[0], i1 = 1.0f / l2[1];
    #pragma unroll
    for (int nt = 0; nt < 8; nt++) {
        size_t row0 = (size_t)(b * SEQ + q0 + qrow + g) * DMODEL + h * HDIM + nt * 8 + t * 2;
        size_t row1 = row0 + 8 * DMODEL;
        __half hh0, hh1, ll0, ll1;
        split_f16(o[nt][0] * i0, hh0, ll0);
        split_f16(o[nt][1] * i0, hh1, ll1);
        *(uint32_t*)(oh + row0) = packh2(hh0, hh1);
        *(uint32_t*)(ol + row0) = packh2(ll0, ll1);
        split_f16(o[nt][2] * i1, hh0, ll0);
        split_f16(o[nt][3] * i1, hh1, ll1);
        *(uint32_t*)(oh + row1) = packh2(hh0, hh1);
        *(uint32_t*)(ol + row1) = packh2(ll0, ll1);
    }
}

// ---------------- host driver ----------------
extern "C" void kernel_launch(void* const* d_in, const int* in_sizes, int n_in,
                              void* d_out, int out_size)
{
    const float* x     = (const float*)d_in[0];
    const int*   mask  = (const int*)d_in[1];
    const float* Wq    = (const float*)d_in[2];
    const float* Wk    = (const float*)d_in[3];
    const float* Wv    = (const float*)d_in[4];
    const float* Wo    = (const float*)d_in[5];
    const float* ln1_g = (const float*)d_in[6];
    const float* ln1_b = (const float*)d_in[7];
    const float* ln2_g = (const float*)d_in[8];
    const float* ln2_b = (const float*)d_in[9];
    const float* W1    = (const float*)d_in[10];
    const float* b1    = (const float*)d_in[11];
    const float* W2    = (const float*)d_in[12];
    const float* b2    = (const float*)d_in[13];

    static float *px = nullptr, *pqkv;
    static __half *plnh, *plnl, *ppah, *ppal, *ppfh, *ppfl, *pwh;
    if (!px) {
        cudaGetSymbolAddress((void**)&pqkv, g_qkv);
        cudaGetSymbolAddress((void**)&plnh, g_lnh);
        cudaGetSymbolAddress((void**)&plnl, g_lnl);
        cudaGetSymbolAddress((void**)&ppah, g_pah);
        cudaGetSymbolAddress((void**)&ppal, g_pal);
        cudaGetSymbolAddress((void**)&ppfh, g_pfh);
        cudaGetSymbolAddress((void**)&ppfl, g_pfl);
        cudaGetSymbolAddress((void**)&pwh, g_wth);
        cudaFuncSetAttribute(attn_mma, cudaFuncAttributeMaxDynamicSharedMemorySize, ATT_SMEM);
        cudaFuncSetAttribute(gemm_pipe<0,1,0>, cudaFuncAttributeMaxDynamicSharedMemorySize, GEMM_SMEM2);
        cudaFuncSetAttribute(gemm_pipe<1,1,0>, cudaFuncAttributeMaxDynamicSharedMemorySize, GEMM_SMEM2);
        cudaFuncSetAttribute(gemm_pipe<2,0,1>, cudaFuncAttributeMaxDynamicSharedMemorySize, GEMM_SMEM2);
        cudaFuncSetAttribute(gemm_pipe<3,1,0>, cudaFuncAttributeMaxDynamicSharedMemorySize, GEMM_SMEM2);
        cudaGetSymbolAddress((void**)&px, g_x);
    }

    // ---- weight convert+transpose (fp16 single) ----
    {
        dim3 blk(32, 8);
        for (int l = 0; l < NLAYERS; l++) {
            size_t base = (size_t)l * WLAYER;
            dim3 gDD(DMODEL / 32, DMODEL / 32);
            wconv_kernel<<<gDD, blk>>>(Wq + (size_t)l * DMODEL * DMODEL, pwh + base,           DMODEL, DMODEL);
            wconv_kernel<<<gDD, blk>>>(Wk + (size_t)l * DMODEL * DMODEL, pwh + base + 262144,  DMODEL, DMODEL);
            wconv_kernel<<<gDD, blk>>>(Wv + (size_t)l * DMODEL * DMODEL, pwh + base + 524288,  DMODEL, DMODEL);
            wconv_kernel<<<gDD, blk>>>(Wo + (size_t)l * DMODEL * DMODEL, pwh + base + 786432,  DMODEL, DMODEL);
            dim3 g1(DFF / 32, DMODEL / 32);
            wconv_kernel<<<g1, blk>>>(W1 + (size_t)l * DMODEL * DFF,     pwh + base + 1048576, DMODEL, DFF);
            dim3 g2(DMODEL / 32, DFF / 32);
            wconv_kernel<<<g2, blk>>>(W2 + (size_t)l * DFF * DMODEL,     pwh + base + 2097152, DFF, DMODEL);
        }
    }

    posenc_kernel<<<(MROWS * DMODEL + 255) / 256, 256>>>(x, px);

    dim3 gQ(QKVN / 128,   MROWS / 128);
    dim3 gD(DMODEL / 128, MROWS / 128);
    dim3 gF(DFF / 128,    MROWS / 128);
    dim3 gA(SEQ / 128, BATCH * NHEAD);

    for (int l = 0; l < NLAYERS; l++) {
        size_t base = (size_t)l * WLAYER;
        const __half *qkvh = pwh + base;
        const __half *ohp  = pwh + base + 786432;
        const __half *f1h  = pwh + base + 1048576;
        const __half *f2h  = pwh + base + 2097152;

        ln_kernel<<<MROWS, 128>>>(px, ln1_g + l * DMODEL, ln1_b + l * DMODEL, plnh, plnl);

        gemm_pipe<0,1,0><<<gQ, 256, GEMM_SMEM2>>>(plnh, plnl, qkvh, nullptr, nullptr,
                                                  pqkv, nullptr, nullptr, DMODEL, QKVN);

        attn_mma<<<gA, 256, ATT_SMEM>>>(pqkv, mask, ppah, ppal);

        gemm_pipe<1,1,0><<<gD, 256, GEMM_SMEM2>>>(ppah, ppal, ohp, nullptr, px,
                                                  px, nullptr, nullptr, DMODEL, DMODEL);

        ln_kernel<<<MROWS, 128>>>(px, ln2_g + l * DMODEL, ln2_b + l * DMODEL, plnh, plnl);

        gemm_pipe<2,0,1><<<gF, 256, GEMM_SMEM2>>>(plnh, plnl, f1h, b1 + (size_t)l * DFF, nullptr,
                                                  nullptr, ppfh, ppfl, DMODEL, DFF);

        float* outp = (l == NLAYERS - 1) ? (float*)d_out : px;
        gemm_pipe<3,1,0><<<gD, 256, GEMM_SMEM2>>>(ppfh, ppfl, f2h, b2 + (size_t)l * DMODEL, px,
                                                  outp, nullptr, nullptr, DFF, DMODEL);
    }
}

// round 9
// speedup vs baseline: 5.0703x; 1.4639x over previous
#include <cuda_runtime.h>
#include <cuda_fp16.h>
#include <math.h>
#include <stdint.h>

// ---------------- problem constants ----------------
#define NLAYERS 4
#define DMODEL  512
#define NHEAD   8
#define HDIM    64
#define DFF     2048
#define BATCH   8
#define SEQ     1024
#define MROWS   (BATCH*SEQ)
#define LN_EPS  1e-3f
#define QKVN    1536

#define WLAYER  3145728
#define WT_ELEMS (NLAYERS*WLAYER)

// ---------------- device scratch ----------------
__device__ float g_x   [MROWS*DMODEL];
__device__ float g_qkv [MROWS*QKVN];
__device__ __half g_lnh[MROWS*DMODEL];
__device__ __half g_pah[MROWS*DMODEL];
__device__ __half g_pfh[MROWS*DFF];
__device__ uint4 g_wth [WT_ELEMS/8];     // weights fp16, [N][K] transposed

extern __shared__ char dyn_smem[];

// ---------------- helpers ----------------
__device__ __forceinline__ void mma16816h(float* c, const uint32_t* a, uint32_t b0, uint32_t b1) {
    asm volatile(
        "mma.sync.aligned.m16n8k16.row.col.f32.f16.f16.f32 "
        "{%0,%1,%2,%3}, {%4,%5,%6,%7}, {%8,%9}, {%0,%1,%2,%3};"
        : "+f"(c[0]), "+f"(c[1]), "+f"(c[2]), "+f"(c[3])
        : "r"(a[0]), "r"(a[1]), "r"(a[2]), "r"(a[3]), "r"(b0), "r"(b1));
}
__device__ __forceinline__ void cpasync16(uint32_t saddr, const void* gptr) {
    asm volatile("cp.async.cg.shared.global [%0], [%1], 16;" :: "r"(saddr), "l"(gptr));
}
__device__ __forceinline__ uint32_t smem_u32(const void* p) {
    uint32_t a;
    asm("{ .reg .u64 t; cvta.to.shared.u64 t, %1; cvt.u32.u64 %0, t; }" : "=r"(a) : "l"(p));
    return a;
}
__device__ __forceinline__ void cp_commit() { asm volatile("cp.async.commit_group;" ::: "memory"); }
__device__ __forceinline__ void cp_wait1()  { asm volatile("cp.async.wait_group 1;"  ::: "memory"); }
__device__ __forceinline__ void cp_wait0()  { asm volatile("cp.async.wait_group 0;"  ::: "memory"); }

__device__ __forceinline__ uint32_t packh2(__half a, __half b) {
    return (uint32_t)__half_as_ushort(a) | ((uint32_t)__half_as_ushort(b) << 16);
}
__device__ __forceinline__ uint32_t ph2(float x, float y) {
    __half2 h = __floats2half2_rn(x, y);
    return *(uint32_t*)&h;
}

// ---------------- positional encoding ----------------
__global__ void posenc_kernel(const float* __restrict__ x, float* __restrict__ out) {
    int idx = blockIdx.x * 256 + threadIdx.x;
    if (idx >= MROWS * DMODEL) return;
    int d = idx & (DMODEL - 1);
    int s = (idx / DMODEL) & (SEQ - 1);
    const int half = DMODEL / 2;
    float val;
    if (d < half) {
        float ang = (float)s * expf(-logf(10000.0f) * (2.0f * (float)d / (float)DMODEL));
        val = sinf(ang);
    } else {
        float j = (float)(d - half);
        float ang = (float)s * expf(-logf(10000.0f) * (2.0f * j / (float)DMODEL));
        val = cosf(ang);
    }
    out[idx] = x[idx] + val;
}

// ---------------- layernorm -> fp16 ----------------
__global__ void ln_kernel(const float* __restrict__ x, const float* __restrict__ gamma,
                          const float* __restrict__ beta, __half* __restrict__ oh) {
    int row = blockIdx.x;
    int t = threadIdx.x;
    const float4* xr = (const float4*)(x + (size_t)row * DMODEL);
    float4 v = xr[t];

    __shared__ float red1[4];
    __shared__ float red2[4];

    float s = v.x + v.y + v.z + v.w;
    #pragma unroll
    for (int o = 16; o > 0; o >>= 1) s += __shfl_xor_sync(0xffffffffu, s, o);
    if ((t & 31) == 0) red1[t >> 5] = s;
    __syncthreads();
    float mean = (red1[0] + red1[1] + red1[2] + red1[3]) * (1.0f / DMODEL);

    float dx = v.x - mean, dy = v.y - mean, dz = v.z - mean, dw = v.w - mean;
    float s2 = dx*dx + dy*dy + dz*dz + dw*dw;
    #pragma unroll
    for (int o = 16; o > 0; o >>= 1) s2 += __shfl_xor_sync(0xffffffffu, s2, o);
    if ((t & 31) == 0) red2[t >> 5] = s2;
    __syncthreads();
    float var = (red2[0] + red2[1] + red2[2] + red2[3]) * (1.0f / DMODEL);
    float rs = rsqrtf(var + LN_EPS);

    float4 g4 = ((const float4*)gamma)[t];
    float4 b4 = ((const float4*)beta)[t];
    float o0 = dx * rs * g4.x + b4.x;
    float o1 = dy * rs * g4.y + b4.y;
    float o2 = dz * rs * g4.z + b4.z;
    float o3 = dw * rs * g4.w + b4.w;
    *(uint2*)(oh + (size_t)row * DMODEL + t * 4) =
        make_uint2(ph2(o0, o1), ph2(o2, o3));
}

// ---------------- weight convert+transpose: fp32 [K][N] -> fp16 [N][K] ----------------
__global__ void wconv_kernel(const float* __restrict__ W, __half* __restrict__ Oh,
                             int K, int N) {
    __shared__ float tile[32][33];
    int tn = blockIdx.x * 32, tk = blockIdx.y * 32;
    int tx = threadIdx.x, ty = threadIdx.y;
    #pragma unroll
    for (int i = 0; i < 4; i++)
        tile[ty + i * 8][tx] = W[(size_t)(tk + ty + i * 8) * N + tn + tx];
    __syncthreads();
    #pragma unroll
    for (int i = 0; i < 4; i++) {
        int nl = ty + i * 8;
        Oh[(size_t)(tn + nl) * K + tk + tx] = __float2half_rn(tile[tx][nl]);
    }
}

// ---------------- pipelined single-fp16 mma GEMM ----------------
// C = A[M,K](fp16) @ W[K,N](fp16 [N][K]).
// EPI: 0 plain, 1 +res, 2 relu(+bias), 3 +bias+res;  OUTF32 / OUTF16 outputs.
#define BKP 20
#define ARR_STRIDE (128 * BKP)
#define STAGE_BYTES (2 * ARR_STRIDE * 4)      // 20480
#define GEMM_SMEM2 (2 * STAGE_BYTES)          // 40960

template<int EPI, int OUTF32, int OUTF16>
__global__ __launch_bounds__(256) void gemm_pipe(
    const __half* __restrict__ Ah,
    const __half* __restrict__ Wh,
    const float* __restrict__ bias, const float* __restrict__ res,
    float* __restrict__ Cf, __half* __restrict__ Ch,
    int K, int N)
{
    uint32_t sbase = smem_u32(dyn_smem);
    int tid = threadIdx.x;
    int lane = tid & 31, wid = tid >> 5;
    int wm = wid >> 1, wn = wid & 1;
    int m0 = blockIdx.y * 128, n0 = blockIdx.x * 128;
    int g = lane >> 2, t = lane & 3;

    int lrow = tid >> 1;
    int lhalf = tid & 1;

    const __half* agh = Ah + (size_t)(m0 + lrow) * K;
    const __half* bgh = Wh + (size_t)(n0 + lrow) * K;
    uint32_t srow = sbase + (uint32_t)(lrow * BKP) * 4;

    auto issue_load = [&](int kb, int st) {
        uint32_t so = srow + (uint32_t)st * STAGE_BYTES;
        #pragma unroll
        for (int p = 0; p < 2; p++) {
            int q = lhalf * 2 + p;
            int ge = kb + q * 8;
            uint32_t sb2 = so + (uint32_t)(q * 16);
            cpasync16(sb2,                  agh + ge);
            cpasync16(sb2 + ARR_STRIDE * 4, bgh + ge);
        }
        cp_commit();
    };

    float c[2][8][4];
    #pragma unroll
    for (int mt = 0; mt < 2; mt++)
        #pragma unroll
        for (int nt = 0; nt < 8; nt++)
            #pragma unroll
            for (int e = 0; e < 4; e++) c[mt][nt][e] = 0.0f;

    const int nkb = K >> 5;
    issue_load(0, 0);

    for (int kb = 0; kb < nkb; kb++) {
        int st = kb & 1;
        if (kb + 1 < nkb) issue_load((kb + 1) << 5, st ^ 1);
        if (kb + 1 < nkb) cp_wait1(); else cp_wait0();
        __syncthreads();

        uint32_t* As_h = (uint32_t*)(dyn_smem + st * STAGE_BYTES);
        uint32_t* Bs_h = As_h + ARR_STRIDE;

        #pragma unroll
        for (int s = 0; s < 2; s++) {
            uint32_t ahf[2][4];
            #pragma unroll
            for (int mt = 0; mt < 2; mt++) {
                int base = (wm * 32 + mt * 16 + g) * BKP + s * 8 + t;
                ahf[mt][0] = As_h[base];
                ahf[mt][1] = As_h[base + 8 * BKP];
                ahf[mt][2] = As_h[base + 4];
                ahf[mt][3] = As_h[base + 8 * BKP + 4];
            }
            #pragma unroll
            for (int nt = 0; nt < 8; nt++) {
                int bbase = (wn * 64 + nt * 8 + g) * BKP + s * 8 + t;
                uint32_t bh0 = Bs_h[bbase], bh1 = Bs_h[bbase + 4];
                #pragma unroll
                for (int mt = 0; mt < 2; mt++)
                    mma16816h(c[mt][nt], ahf[mt], bh0, bh1);
            }
        }
        __syncthreads();
    }

    #pragma unroll
    for (int mt = 0; mt < 2; mt++) {
        #pragma unroll
        for (int nt = 0; nt < 8; nt++) {
            int row = m0 + wm * 32 + mt * 16 + g;
            int col = n0 + wn * 64 + nt * 8 + t * 2;
            float2 v1 = make_float2(c[mt][nt][0], c[mt][nt][1]);
            float2 v2 = make_float2(c[mt][nt][2], c[mt][nt][3]);
            if (EPI == 2 || EPI == 3) {
                float2 bb = *(const float2*)(bias + col);
                v1.x += bb.x; v1.y += bb.y;
                v2.x += bb.x; v2.y += bb.y;
            }
            if (EPI == 2) {
                v1.x = fmaxf(v1.x, 0.0f); v1.y = fmaxf(v1.y, 0.0f);
                v2.x = fmaxf(v2.x, 0.0f); v2.y = fmaxf(v2.y, 0.0f);
            }
            if (EPI == 1 || EPI == 3) {
                float2 r1 = *(const float2*)(res + (size_t)row * N + col);
                float2 r2 = *(const float2*)(res + (size_t)(row + 8) * N + col);
                v1.x += r1.x; v1.y += r1.y;
                v2.x += r2.x; v2.y += r2.y;
            }
            if (OUTF32) {
                *(float2*)(Cf + (size_t)row * N + col) = v1;
                *(float2*)(Cf + (size_t)(row + 8) * N + col) = v2;
            }
            if (OUTF16) {
                *(uint32_t*)(Ch + (size_t)row * N + col) = ph2(v1.x, v1.y);
                *(uint32_t*)(Ch + (size_t)(row + 8) * N + col) = ph2(v2.x, v2.y);
            }
        }
    }
}

// ---------------- tensor-core flash attention (fp16 mma) ----------------
#define AQP 36
#define ATT_SMEM (((128 + 64 + 64) * AQP) * 4 + 256)

__global__ __launch_bounds__(256) void attn_mma(
    const float* __restrict__ qkv, const int* __restrict__ mask,
    __half* __restrict__ oh)
{
    uint32_t* Qs = (uint32_t*)dyn_smem;
    uint32_t* Ks = Qs + 128 * AQP;
    uint32_t* Vt = Ks + 64 * AQP;
    float* mb = (float*)(Vt + 64 * AQP);

    int tid = threadIdx.x;
    int lane = tid & 31, wid = tid >> 5;
    int g = lane >> 2, t = lane & 3;
    int b = blockIdx.y >> 3, h = blockIdx.y & 7;
    int q0 = blockIdx.x * 128;
    const float scale = 0.125f;

    #pragma unroll
    for (int p = 0; p < 8; p++) {
        int idx = tid + p * 256;
        int row = idx >> 4, c4 = (idx & 15) * 4;
        float4 f = *(const float4*)(qkv + (size_t)(b * SEQ + q0 + row) * QKVN + h * HDIM + c4);
        Qs[row * AQP + c4 / 2]     = ph2(f.x, f.y);
        Qs[row * AQP + c4 / 2 + 1] = ph2(f.z, f.w);
    }

    float m2[2] = {-INFINITY, -INFINITY};
    float l2[2] = {0.0f, 0.0f};
    float o[8][4];
    #pragma unroll
    for (int nt = 0; nt < 8; nt++)
        #pragma unroll
        for (int e = 0; e < 4; e++) o[nt][e] = 0.0f;

    int qrow = wid * 16;

    for (int kt = 0; kt < SEQ / 64; kt++) {
        __syncthreads();
        #pragma unroll
        for (int p = 0; p < 4; p++) {
            int idx = tid + p * 256;
            int row = idx >> 4, c4 = (idx & 15) * 4;
            float4 f = *(const float4*)(qkv + (size_t)(b * SEQ + kt * 64 + row) * QKVN + DMODEL + h * HDIM + c4);
            Ks[row * AQP + c4 / 2]     = ph2(f.x, f.y);
            Ks[row * AQP + c4 / 2 + 1] = ph2(f.z, f.w);
        }
        #pragma unroll
        for (int it = 0; it < 2; it++) {
            int hd0 = ((tid >> 5) + it * 8) * 4;
            int kp = tid & 31;
            const float* v0 = qkv + (size_t)(b * SEQ + kt * 64 + kp * 2) * QKVN + 2 * DMODEL + h * HDIM + hd0;
            float4 fa = *(const float4*)v0;
            float4 fb = *(const float4*)(v0 + QKVN);
            Vt[(hd0 + 0) * AQP + kp] = ph2(fa.x, fb.x);
            Vt[(hd0 + 1) * AQP + kp] = ph2(fa.y, fb.y);
            Vt[(hd0 + 2) * AQP + kp] = ph2(fa.z, fb.z);
            Vt[(hd0 + 3) * AQP + kp] = ph2(fa.w, fb.w);
        }
        if (tid < 64)
            mb[tid] = (mask[b * SEQ + kt * 64 + tid] != 0) ? 0.0f : -1e9f;
        __syncthreads();

        float sv[8][4];
        #pragma unroll
        for (int nt = 0; nt < 8; nt++)
            #pragma unroll
            for (int e = 0; e < 4; e++) sv[nt][e] = 0.0f;

        #pragma unroll
        for (int s = 0; s < 4; s++) {
            uint32_t a[4];
            int ab = (qrow + g) * AQP + s * 8 + t;
            a[0] = Qs[ab];
            a[1] = Qs[ab + 8 * AQP];
            a[2] = Qs[ab + 4];
            a[3] = Qs[ab + 8 * AQP + 4];
            #pragma unroll
            for (int nt = 0; nt < 8; nt++) {
                int bb = (nt * 8 + g) * AQP + s * 8 + t;
                mma16816h(sv[nt], a, Ks[bb], Ks[bb + 4]);
            }
        }

        float rm0 = -INFINITY, rm1 = -INFINITY;
        #pragma unroll
        for (int nt = 0; nt < 8; nt++) {
            int col = nt * 8 + t * 2;
            float mb0 = mb[col], mb1 = mb[col + 1];
            sv[nt][0] = sv[nt][0] * scale + mb0;
            sv[nt][1] = sv[nt][1] * scale + mb1;
            sv[nt][2] = sv[nt][2] * scale + mb0;
            sv[nt][3] = sv[nt][3] * scale + mb1;
            rm0 = fmaxf(rm0, fmaxf(sv[nt][0], sv[nt][1]));
            rm1 = fmaxf(rm1, fmaxf(sv[nt][2], sv[nt][3]));
        }
        #pragma unroll
        for (int ox = 1; ox <= 2; ox <<= 1) {
            rm0 = fmaxf(rm0, __shfl_xor_sync(0xffffffffu, rm0, ox));
            rm1 = fmaxf(rm1, __shfl_xor_sync(0xffffffffu, rm1, ox));
        }
        float mn0 = fmaxf(m2[0], rm0), mn1 = fmaxf(m2[1], rm1);
        float f0 = __expf(m2[0] - mn0), f1 = __expf(m2[1] - mn1);
        m2[0] = mn0; m2[1] = mn1;

        float rs0 = 0.0f, rs1 = 0.0f;
        #pragma unroll
        for (int nt = 0; nt < 8; nt++) {
            sv[nt][0] = __expf(sv[nt][0] - mn0);
            sv[nt][1] = __expf(sv[nt][1] - mn0);
            sv[nt][2] = __expf(sv[nt][2] - mn1);
            sv[nt][3] = __expf(sv[nt][3] - mn1);
            rs0 += sv[nt][0] + sv[nt][1];
            rs1 += sv[nt][2] + sv[nt][3];
        }
        #pragma unroll
        for (int ox = 1; ox <= 2; ox <<= 1) {
            rs0 += __shfl_xor_sync(0xffffffffu, rs0, ox);
            rs1 += __shfl_xor_sync(0xffffffffu, rs1, ox);
        }
        l2[0] = l2[0] * f0 + rs0;
        l2[1] = l2[1] * f1 + rs1;
        #pragma unroll
        for (int nt = 0; nt < 8; nt++) {
            o[nt][0] *= f0; o[nt][1] *= f0;
            o[nt][2] *= f1; o[nt][3] *= f1;
        }

        #pragma unroll
        for (int s = 0; s < 4; s++) {
            uint32_t a[4];
            a[0] = ph2(sv[2 * s][0],     sv[2 * s][1]);
            a[1] = ph2(sv[2 * s][2],     sv[2 * s][3]);
            a[2] = ph2(sv[2 * s + 1][0], sv[2 * s + 1][1]);
            a[3] = ph2(sv[2 * s + 1][2], sv[2 * s + 1][3]);
            #pragma unroll
            for (int nt = 0; nt < 8; nt++) {
                int bb = (nt * 8 + g) * AQP + s * 8 + t;
                mma16816h(o[nt], a, Vt[bb], Vt[bb + 4]);
            }
        }
    }

    float i0 = 1.0f / l2[0], i1 = 1.0f / l2[1];
    #pragma unroll
    for (int nt = 0; nt < 8; nt++) {
        size_t row0 = (size_t)(b * SEQ + q0 + qrow + g) * DMODEL + h * HDIM + nt * 8 + t * 2;
        size_t row1 = row0 + 8 * DMODEL;
        *(uint32_t*)(oh + row0) = ph2(o[nt][0] * i0, o[nt][1] * i0);
        *(uint32_t*)(oh + row1) = ph2(o[nt][2] * i1, o[nt][3] * i1);
    }
}

// ---------------- host driver ----------------
extern "C" void kernel_launch(void* const* d_in, const int* in_sizes, int n_in,
                              void* d_out, int out_size)
{
    const float* x     = (const float*)d_in[0];
    const int*   mask  = (const int*)d_in[1];
    const float* Wq    = (const float*)d_in[2];
    const float* Wk    = (const float*)d_in[3];
    const float* Wv    = (const float*)d_in[4];
    const float* Wo    = (const float*)d_in[5];
    const float* ln1_g = (const float*)d_in[6];
    const float* ln1_b = (const float*)d_in[7];
    const float* ln2_g = (const float*)d_in[8];
    const float* ln2_b = (const float*)d_in[9];
    const float* W1    = (const float*)d_in[10];
    const float* b1    = (const float*)d_in[11];
    const float* W2    = (const float*)d_in[12];
    const float* b2    = (const float*)d_in[13];

    static float *px = nullptr, *pqkv;
    static __half *plnh, *ppah, *ppfh, *pwh;
    if (!px) {
        cudaGetSymbolAddress((void**)&pqkv, g_qkv);
        cudaGetSymbolAddress((void**)&plnh, g_lnh);
        cudaGetSymbolAddress((void**)&ppah, g_pah);
        cudaGetSymbolAddress((void**)&ppfh, g_pfh);
        cudaGetSymbolAddress((void**)&pwh, g_wth);
        cudaFuncSetAttribute(attn_mma, cudaFuncAttributeMaxDynamicSharedMemorySize, ATT_SMEM);
        cudaFuncSetAttribute(gemm_pipe<0,1,0>, cudaFuncAttributeMaxDynamicSharedMemorySize, GEMM_SMEM2);
        cudaFuncSetAttribute(gemm_pipe<1,1,0>, cudaFuncAttributeMaxDynamicSharedMemorySize, GEMM_SMEM2);
        cudaFuncSetAttribute(gemm_pipe<2,0,1>, cudaFuncAttributeMaxDynamicSharedMemorySize, GEMM_SMEM2);
        cudaFuncSetAttribute(gemm_pipe<3,1,0>, cudaFuncAttributeMaxDynamicSharedMemorySize, GEMM_SMEM2);
        cudaGetSymbolAddress((void**)&px, g_x);
    }

    // ---- weight convert+transpose (fp16 single) ----
    {
        dim3 blk(32, 8);
        for (int l = 0; l < NLAYERS; l++) {
            size_t base = (size_t)l * WLAYER;
            dim3 gDD(DMODEL / 32, DMODEL / 32);
            wconv_kernel<<<gDD, blk>>>(Wq + (size_t)l * DMODEL * DMODEL, pwh + base,           DMODEL, DMODEL);
            wconv_kernel<<<gDD, blk>>>(Wk + (size_t)l * DMODEL * DMODEL, pwh + base + 262144,  DMODEL, DMODEL);
            wconv_kernel<<<gDD, blk>>>(Wv + (size_t)l * DMODEL * DMODEL, pwh + base + 524288,  DMODEL, DMODEL);
            wconv_kernel<<<gDD, blk>>>(Wo + (size_t)l * DMODEL * DMODEL, pwh + base + 786432,  DMODEL, DMODEL);
            dim3 g1(DFF / 32, DMODEL / 32);
            wconv_kernel<<<g1, blk>>>(W1 + (size_t)l * DMODEL * DFF,     pwh + base + 1048576, DMODEL, DFF);
            dim3 g2(DMODEL / 32, DFF / 32);
            wconv_kernel<<<g2, blk>>>(W2 + (size_t)l * DFF * DMODEL,     pwh + base + 2097152, DFF, DMODEL);
        }
    }

    posenc_kernel<<<(MROWS * DMODEL + 255) / 256, 256>>>(x, px);

    dim3 gQ(QKVN / 128,   MROWS / 128);
    dim3 gD(DMODEL / 128, MROWS / 128);
    dim3 gF(DFF / 128,    MROWS / 128);
    dim3 gA(SEQ / 128, BATCH * NHEAD);

    for (int l = 0; l < NLAYERS; l++) {
        size_t base = (size_t)l * WLAYER;
        const __half *qkvh = pwh + base;
        const __half *ohp  = pwh + base + 786432;
        const __half *f1h  = pwh + base + 1048576;
        const __half *f2h  = pwh + base + 2097152;

        ln_kernel<<<MROWS, 128>>>(px, ln1_g + l * DMODEL, ln1_b + l * DMODEL, plnh);

        gemm_pipe<0,1,0><<<gQ, 256, GEMM_SMEM2>>>(plnh, qkvh, nullptr, nullptr,
                                                  pqkv, nullptr, DMODEL, QKVN);

        attn_mma<<<gA, 256, ATT_SMEM>>>(pqkv, mask, ppah);

        gemm_pipe<1,1,0><<<gD, 256, GEMM_SMEM2>>>(ppah, ohp, nullptr, px,
                                                  px, nullptr, DMODEL, DMODEL);

        ln_kernel<<<MROWS, 128>>>(px, ln2_g + l * DMODEL, ln2_b + l * DMODEL, plnh);

        gemm_pipe<2,0,1><<<gF, 256, GEMM_SMEM2>>>(plnh, f1h, b1 + (size_t)l * DFF, nullptr,
                                                  nullptr, ppfh, DMODEL, DFF);

        float* outp = (l == NLAYERS - 1) ? (float*)d_out : px;
        gemm_pipe<3,1,0><<<gD, 256, GEMM_SMEM2>>>(ppfh, f2h, b2 + (size_t)l * DMODEL, px,
                                                  outp, nullptr, DFF, DMODEL);
    }
}